// round 7
// baseline (speedup 1.0000x reference)
#include <cuda_runtime.h>
#include <cuda_bf16.h>
#include <cstdint>

// Problem constants
#define DIN   128
#define DOUT  128
#define DEG   48
#define KSEL  32
#define NPAD  50048

__device__ float g_x[(size_t)NPAD * DOUT];                 // fp32 (agg path)
__device__ __nv_bfloat16 g_xhi[(size_t)NPAD * DOUT];       // truncation hi
__device__ __nv_bfloat16 g_xlo[(size_t)NPAD * DOUT];       // residual lo
__device__ __nv_bfloat16 g_wThi[128 * 128];                // W^T hi, [n][k]
__device__ __nv_bfloat16 g_wTlo[128 * 128];                // W^T lo, [n][k]

// ---------------------------------------------------------------------------
// Common helpers
// ---------------------------------------------------------------------------
__device__ __forceinline__ uint32_t smem_u32(const void* p) {
    uint32_t a;
    asm("{ .reg .u64 t; cvta.to.shared.u64 t, %1; cvt.u32.u64 %0, t; }" : "=r"(a) : "l"(p));
    return a;
}

__device__ __forceinline__ void ldmatrix_x4(uint32_t* r, uint32_t addr) {
    asm volatile("ldmatrix.sync.aligned.m8n8.x4.shared.b16 {%0,%1,%2,%3}, [%4];"
                 : "=r"(r[0]), "=r"(r[1]), "=r"(r[2]), "=r"(r[3]) : "r"(addr));
}

__device__ __forceinline__ void mma_bf16(float* c, const uint32_t* a, const uint32_t* b) {
    asm volatile(
        "mma.sync.aligned.m16n8k16.row.col.f32.bf16.bf16.f32 "
        "{%0,%1,%2,%3}, {%4,%5,%6,%7}, {%8,%9}, {%0,%1,%2,%3};"
        : "+f"(c[0]), "+f"(c[1]), "+f"(c[2]), "+f"(c[3])
        : "r"(a[0]), "r"(a[1]), "r"(a[2]), "r"(a[3]), "r"(b[0]), "r"(b[1]));
}

// Truncation split: hi = top-16 bits of fp32, lo = rn-bf16 of (x - hi).
__device__ __forceinline__ void split4(float4 v, uint2& hp, uint2& lp) {
    uint32_t ax = __float_as_uint(v.x), ay = __float_as_uint(v.y);
    uint32_t az = __float_as_uint(v.z), aw = __float_as_uint(v.w);
    hp.x = __byte_perm(ax, ay, 0x7632);
    hp.y = __byte_perm(az, aw, 0x7632);
    float lx = v.x - __uint_as_float(ax & 0xffff0000u);
    float ly = v.y - __uint_as_float(ay & 0xffff0000u);
    float lz = v.z - __uint_as_float(az & 0xffff0000u);
    float lw = v.w - __uint_as_float(aw & 0xffff0000u);
    asm("cvt.rn.bf16x2.f32 %0, %1, %2;" : "=r"(lp.x) : "f"(ly), "f"(lx));
    asm("cvt.rn.bf16x2.f32 %0, %1, %2;" : "=r"(lp.y) : "f"(lw), "f"(lz));
}

// pair split for float2 (epilogue)
__device__ __forceinline__ void split2(float x, float y, uint32_t& hp, uint32_t& lp) {
    uint32_t ax = __float_as_uint(x), ay = __float_as_uint(y);
    hp = __byte_perm(ax, ay, 0x7632);
    float lx = x - __uint_as_float(ax & 0xffff0000u);
    float ly = y - __uint_as_float(ay & 0xffff0000u);
    asm("cvt.rn.bf16x2.f32 %0, %1, %2;" : "=r"(lp) : "f"(ly), "f"(lx));
}

// ---------------------------------------------------------------------------
// Kernel 0: transpose + split W -> g_wThi/g_wTlo  ([n][k] bf16)
// ---------------------------------------------------------------------------
__global__ __launch_bounds__(256) void wsplit_kernel(const float* __restrict__ W)
{
    int idx = blockIdx.x * 256 + threadIdx.x;
    int k = idx >> 7, nn = idx & 127;
    float v = W[k * 128 + nn];
    uint32_t b = __float_as_uint(v);
    uint32_t hbits = b & 0xffff0000u;
    float lo = v - __uint_as_float(hbits);
    g_wThi[nn * 128 + k] = __ushort_as_bfloat16((unsigned short)(hbits >> 16));
    g_wTlo[nn * 128 + k] = __float2bfloat16_rn(lo);
}

// ---------------------------------------------------------------------------
// Kernel A: x = feat @ W via bf16 3-pass mma.sync; epilogue emits fp32 + hi/lo
// ---------------------------------------------------------------------------
#define GAP 40   // bf16 smem pitch (80 B), ldmatrix conflict-free

__global__ __launch_bounds__(256) void gemm_kernel(const float* __restrict__ feat,
                                                   int n)
{
    __shared__ __align__(16) __nv_bfloat16 sa_h[128 * GAP];
    __shared__ __align__(16) __nv_bfloat16 sa_l[128 * GAP];
    __shared__ __align__(16) __nv_bfloat16 sb_h[128 * GAP];
    __shared__ __align__(16) __nv_bfloat16 sb_l[128 * GAP];

    const int tid  = threadIdx.x;
    const int lane = tid & 31;
    const int wrp  = tid >> 5;
    const int row0 = blockIdx.x * 128;

    const int m0 = (wrp & 1) * 64;
    const int n0 = (wrp >> 1) * 32;
    const int rsel = lane >> 3, rin = lane & 7;

    const uint32_t sah = smem_u32(sa_h), sal = smem_u32(sa_l);
    const uint32_t sbh = smem_u32(sb_h), sbl = smem_u32(sb_l);

    float acc[4][4][4];
#pragma unroll
    for (int mt = 0; mt < 4; ++mt)
#pragma unroll
        for (int nt = 0; nt < 4; ++nt)
#pragma unroll
            for (int i = 0; i < 4; ++i) acc[mt][nt][i] = 0.0f;

    for (int kt = 0; kt < 4; ++kt) {
#pragma unroll
        for (int i = 0; i < 4; ++i) {
            int idx = tid + i * 256;
            int r = idx >> 3, q = idx & 7;
            int rg = row0 + r; if (rg > n - 1) rg = n - 1;
            float4 v = *(const float4*)&feat[(size_t)rg * DIN + kt * 32 + q * 4];
            uint2 hp, lp;
            split4(v, hp, lp);
            *(uint2*)&sa_h[r * GAP + q * 4] = hp;
            *(uint2*)&sa_l[r * GAP + q * 4] = lp;
        }
#pragma unroll
        for (int i = 0; i < 2; ++i) {
            int idx = tid + i * 256;
            int r = idx >> 2, q = idx & 3;
            *(uint4*)&sb_h[r * GAP + q * 8] =
                *(const uint4*)&g_wThi[r * 128 + kt * 32 + q * 8];
            *(uint4*)&sb_l[r * GAP + q * 8] =
                *(const uint4*)&g_wTlo[r * 128 + kt * 32 + q * 8];
        }
        __syncthreads();

#pragma unroll
        for (int kc = 0; kc < 2; ++kc) {
            const uint32_t kadd = kc * 32;
            uint32_t bh[8], bl[8];
#pragma unroll
            for (int h = 0; h < 2; ++h) {
                uint32_t boff = (uint32_t)((n0 + h * 16 + (rsel >> 1) * 8 + rin) * GAP
                                           + (rsel & 1) * 8) * 2 + kadd;
                ldmatrix_x4(&bh[h * 4], sbh + boff);
                ldmatrix_x4(&bl[h * 4], sbl + boff);
            }
#pragma unroll
            for (int mt = 0; mt < 4; ++mt) {
                uint32_t aoff = (uint32_t)((m0 + mt * 16 + (rsel & 1) * 8 + rin) * GAP
                                           + (rsel >> 1) * 8) * 2 + kadd;
                uint32_t ah[4], al[4];
                ldmatrix_x4(ah, sah + aoff);
                ldmatrix_x4(al, sal + aoff);
#pragma unroll
                for (int nt = 0; nt < 4; ++nt) {
                    mma_bf16(acc[mt][nt], ah, &bh[nt * 2]);
                    mma_bf16(acc[mt][nt], ah, &bl[nt * 2]);
                    mma_bf16(acc[mt][nt], al, &bh[nt * 2]);
                }
            }
        }
        __syncthreads();
    }

    // epilogue: fp32 + bf16 hi/lo split (once per row, amortizes node work)
#pragma unroll
    for (int mt = 0; mt < 4; ++mt) {
        int ra = row0 + m0 + mt * 16 + (lane >> 2);
#pragma unroll
        for (int nt = 0; nt < 4; ++nt) {
            int cb = n0 + nt * 8 + 2 * (lane & 3);
            float2 v0 = make_float2(acc[mt][nt][0], acc[mt][nt][1]);
            float2 v1 = make_float2(acc[mt][nt][2], acc[mt][nt][3]);
            *(float2*)&g_x[(size_t)ra * DOUT + cb]       = v0;
            *(float2*)&g_x[(size_t)(ra + 8) * DOUT + cb] = v1;
            uint32_t hp, lp;
            split2(v0.x, v0.y, hp, lp);
            *(uint32_t*)&g_xhi[(size_t)ra * DOUT + cb] = hp;
            *(uint32_t*)&g_xlo[(size_t)ra * DOUT + cb] = lp;
            split2(v1.x, v1.y, hp, lp);
            *(uint32_t*)&g_xhi[(size_t)(ra + 8) * DOUT + cb] = hp;
            *(uint32_t*)&g_xlo[(size_t)(ra + 8) * DOUT + cb] = lp;
        }
    }
}

// ---------------------------------------------------------------------------
// Kernel B: per-node top-k, Gram via 2-pass symmetrized bf16 mma, softmax, agg
// 1 CTA per node, 128 threads (4 warps)
// ---------------------------------------------------------------------------
#define BPITCH 136
#define GPITCH 34

__global__ __launch_bounds__(128) void node_kernel(const float* __restrict__ ew,
                                                   const int*   __restrict__ nbr,
                                                   const float* __restrict__ bias,
                                                   float*       __restrict__ out,
                                                   int n)
{
    __shared__ __align__(16) __nv_bfloat16 xhi[32 * BPITCH];
    __shared__ __align__(16) __nv_bfloat16 xlo[32 * BPITCH];
    __shared__ __align__(16) float sghh[32 * GPITCH];
    __shared__ __align__(16) float sghl[32 * GPITCH];
    __shared__ float sw49[52];
    __shared__ int   sid49[52];
    __shared__ float selw[32];
    __shared__ int   selid[32];
    __shared__ float ssq[32];
    __shared__ float sdist[32];
    __shared__ float srel[32];

    const int node = blockIdx.x;
    const int tid  = threadIdx.x;
    const int lane = tid & 31;
    const int wrp  = tid >> 5;

    // --- load 48 edges + self-loop ---
    if (tid < DEG) {
        sw49[tid]  = ew[(size_t)node * DEG + tid];
        sid49[tid] = nbr[(size_t)node * DEG + tid];
    } else if (tid == DEG) {
        sw49[DEG]  = 1.0f;
        sid49[DEG] = node;
    }
    __syncthreads();

    // --- top-32 of 49 (stable rank = lax.top_k tie-break) ---
    if (tid < DEG + 1) {
        float v = sw49[tid];
        int rank = 0;
#pragma unroll
        for (int j = 0; j < DEG + 1; ++j) {
            float wj = sw49[j];
            rank += (wj > v) || (wj == v && j < tid);
        }
        if (rank < KSEL) {
            selw[rank]  = v;
            selid[rank] = sid49[tid];
        }
    }
    __syncthreads();

    // --- gather pre-split bf16 rows (coalesced 8B per lane) ---
    {
        const int r0 = wrp * 8;
        const int c0 = lane * 4;
#pragma unroll
        for (int r = 0; r < 8; ++r) {
            const int row = r0 + r;
            const size_t base = (size_t)selid[row] * DOUT + c0;
            uint2 h = *(const uint2*)&g_xhi[base];
            uint2 l = *(const uint2*)&g_xlo[base];
            *(uint2*)&xhi[row * BPITCH + c0] = h;
            *(uint2*)&xlo[row * BPITCH + c0] = l;
        }
    }
    __syncthreads();

    // --- Gram 2-pass: C_hh = hi.hi^T, C_hl = hi.lo^T ---
    {
        const int m0 = (wrp & 1) * 16;
        const int n0 = (wrp >> 1) * 16;
        const int rsel = lane >> 3, rin = lane & 7;

        const uint32_t a_off = (uint32_t)((m0 + (rsel & 1) * 8 + rin) * BPITCH
                                          + ((rsel >> 1) * 8)) * 2;
        const uint32_t b_off = (uint32_t)((n0 + (rsel >> 1) * 8 + rin) * BPITCH
                                          + ((rsel & 1) * 8)) * 2;

        const uint32_t hbase = smem_u32(xhi);
        const uint32_t lbase = smem_u32(xlo);

        float chh0[4] = {0.f, 0.f, 0.f, 0.f};
        float chl0[4] = {0.f, 0.f, 0.f, 0.f};
        float chh1[4] = {0.f, 0.f, 0.f, 0.f};
        float chl1[4] = {0.f, 0.f, 0.f, 0.f};

#pragma unroll
        for (int kc = 0; kc < 8; ++kc) {
            const uint32_t kadd = (uint32_t)(kc * 32);
            uint32_t ah[4], bh[4], bl[4];
            ldmatrix_x4(ah, hbase + a_off + kadd);
            ldmatrix_x4(bh, hbase + b_off + kadd);
            ldmatrix_x4(bl, lbase + b_off + kadd);

            mma_bf16(chh0, ah, &bh[0]);
            mma_bf16(chl0, ah, &bl[0]);
            mma_bf16(chh1, ah, &bh[2]);
            mma_bf16(chl1, ah, &bl[2]);
        }

        const int ra = m0 + (lane >> 2);
        const int cb = 2 * (lane & 3);
        *(float2*)&sghh[ra * GPITCH + n0 + cb]           = make_float2(chh0[0], chh0[1]);
        *(float2*)&sghh[(ra + 8) * GPITCH + n0 + cb]     = make_float2(chh0[2], chh0[3]);
        *(float2*)&sghh[ra * GPITCH + n0 + 8 + cb]       = make_float2(chh1[0], chh1[1]);
        *(float2*)&sghh[(ra + 8) * GPITCH + n0 + 8 + cb] = make_float2(chh1[2], chh1[3]);
        *(float2*)&sghl[ra * GPITCH + n0 + cb]           = make_float2(chl0[0], chl0[1]);
        *(float2*)&sghl[(ra + 8) * GPITCH + n0 + cb]     = make_float2(chl0[2], chl0[3]);
        *(float2*)&sghl[ra * GPITCH + n0 + 8 + cb]       = make_float2(chl1[0], chl1[1]);
        *(float2*)&sghl[(ra + 8) * GPITCH + n0 + 8 + cb] = make_float2(chl1[2], chl1[3]);
    }
    __syncthreads();

    if (tid < 32)
        ssq[tid] = sghh[tid * GPITCH + tid] + 2.0f * sghl[tid * GPITCH + tid];
    __syncthreads();

    // --- weighted medoid distances (gram = hh + hl + hl^T) ---
    {
        int a = tid >> 2, q = tid & 3;
        float sqa  = ssq[a];
        float part = 0.0f;
#pragma unroll
        for (int i = 0; i < 8; ++i) {
            int b = q * 8 + i;
            float g = sghh[a * GPITCH + b] + sghl[a * GPITCH + b] + sghl[b * GPITCH + a];
            float d2 = sqa + ssq[b] - 2.0f * g;
            float dm = (d2 > 0.0f) ? sqrtf(d2) : 0.0f;
            part = fmaf(selw[b], dm, part);
        }
        part += __shfl_down_sync(0xffffffffu, part, 2);
        part += __shfl_down_sync(0xffffffffu, part, 1);
        if (q == 0) sdist[a] = part;
    }
    __syncthreads();

    // --- softmax(-dist) * tw, renormalized (warp 0) ---
    if (tid < 32) {
        float v = sdist[tid];
        float m = v;
#pragma unroll
        for (int off = 16; off; off >>= 1)
            m = fminf(m, __shfl_xor_sync(0xffffffffu, m, off));
        float r = expf(m - v) * selw[tid];
        float s = r;
#pragma unroll
        for (int off = 16; off; off >>= 1)
            s += __shfl_xor_sync(0xffffffffu, s, off);
        srel[tid] = r / s;
    }
    __syncthreads();

    // --- out[d] = bias[d] + sum_k rel[k] * x[sel[k]][d]  (fp32 re-gather) ---
    {
        float acc = bias[tid];
#pragma unroll
        for (int k = 0; k < 32; ++k)
            acc = fmaf(srel[k], g_x[(size_t)selid[k] * DOUT + tid], acc);
        out[(size_t)node * DOUT + tid] = acc;
    }
}

// ---------------------------------------------------------------------------
// Launch
// ---------------------------------------------------------------------------
extern "C" void kernel_launch(void* const* d_in, const int* in_sizes, int n_in,
                              void* d_out, int out_size)
{
    const float* feat   = (const float*)d_in[0];
    const float* ew     = (const float*)d_in[1];
    const float* weight = (const float*)d_in[2];
    const float* bias   = (const float*)d_in[3];
    const int*   nbr    = (const int*)  d_in[4];
    float*       out    = (float*)d_out;

    int n = in_sizes[0] / DIN;

    wsplit_kernel<<<64, 256>>>(weight);
    gemm_kernel<<<(n + 127) / 128, 256>>>(feat, n);
    node_kernel<<<n, 128>>>(ew, nbr, bias, out, n);
}

// round 8
// speedup vs baseline: 1.2594x; 1.2594x over previous
#include <cuda_runtime.h>
#include <cuda_bf16.h>
#include <cstdint>

// Problem constants
#define DIN   128
#define DOUT  128
#define DEG   48
#define KSEL  32
#define NPAD  50048

__device__ float g_x[(size_t)NPAD * DOUT];
__device__ __nv_bfloat16 g_wThi[128 * 128];   // W^T hi, [n][k]
__device__ __nv_bfloat16 g_wTlo[128 * 128];   // W^T lo, [n][k]

// ---------------------------------------------------------------------------
// Common helpers
// ---------------------------------------------------------------------------
__device__ __forceinline__ uint32_t smem_u32(const void* p) {
    uint32_t a;
    asm("{ .reg .u64 t; cvta.to.shared.u64 t, %1; cvt.u32.u64 %0, t; }" : "=r"(a) : "l"(p));
    return a;
}

__device__ __forceinline__ void ldmatrix_x4(uint32_t* r, uint32_t addr) {
    asm volatile("ldmatrix.sync.aligned.m8n8.x4.shared.b16 {%0,%1,%2,%3}, [%4];"
                 : "=r"(r[0]), "=r"(r[1]), "=r"(r[2]), "=r"(r[3]) : "r"(addr));
}

__device__ __forceinline__ void mma_bf16(float* c, const uint32_t* a, const uint32_t* b) {
    asm volatile(
        "mma.sync.aligned.m16n8k16.row.col.f32.bf16.bf16.f32 "
        "{%0,%1,%2,%3}, {%4,%5,%6,%7}, {%8,%9}, {%0,%1,%2,%3};"
        : "+f"(c[0]), "+f"(c[1]), "+f"(c[2]), "+f"(c[3])
        : "r"(a[0]), "r"(a[1]), "r"(a[2]), "r"(a[3]), "r"(b[0]), "r"(b[1]));
}

// Truncation split: hi = top-16 bits of fp32, lo = rn-bf16 of (x - hi).
__device__ __forceinline__ void split4(float4 v, uint2& hp, uint2& lp) {
    uint32_t ax = __float_as_uint(v.x), ay = __float_as_uint(v.y);
    uint32_t az = __float_as_uint(v.z), aw = __float_as_uint(v.w);
    hp.x = __byte_perm(ax, ay, 0x7632);
    hp.y = __byte_perm(az, aw, 0x7632);
    float lx = v.x - __uint_as_float(ax & 0xffff0000u);
    float ly = v.y - __uint_as_float(ay & 0xffff0000u);
    float lz = v.z - __uint_as_float(az & 0xffff0000u);
    float lw = v.w - __uint_as_float(aw & 0xffff0000u);
    asm("cvt.rn.bf16x2.f32 %0, %1, %2;" : "=r"(lp.x) : "f"(ly), "f"(lx));
    asm("cvt.rn.bf16x2.f32 %0, %1, %2;" : "=r"(lp.y) : "f"(lw), "f"(lz));
}

// ---------------------------------------------------------------------------
// Kernel 0: transpose + split W -> g_wThi/g_wTlo  ([n][k] bf16)
// ---------------------------------------------------------------------------
__global__ __launch_bounds__(256) void wsplit_kernel(const float* __restrict__ W)
{
    int idx = blockIdx.x * 256 + threadIdx.x;
    int k = idx >> 7, nn = idx & 127;
    float v = W[k * 128 + nn];
    uint32_t b = __float_as_uint(v);
    uint32_t hbits = b & 0xffff0000u;
    float lo = v - __uint_as_float(hbits);
    g_wThi[nn * 128 + k] = __ushort_as_bfloat16((unsigned short)(hbits >> 16));
    g_wTlo[nn * 128 + k] = __float2bfloat16_rn(lo);
}

// ---------------------------------------------------------------------------
// Kernel A: x = feat @ W via bf16 3-pass mma.sync (R5 version, fp32 out only)
// ---------------------------------------------------------------------------
#define GAP 40   // bf16 smem pitch (80 B), ldmatrix conflict-free

__global__ __launch_bounds__(256) void gemm_kernel(const float* __restrict__ feat,
                                                   int n)
{
    __shared__ __align__(16) __nv_bfloat16 sa_h[128 * GAP];
    __shared__ __align__(16) __nv_bfloat16 sa_l[128 * GAP];
    __shared__ __align__(16) __nv_bfloat16 sb_h[128 * GAP];
    __shared__ __align__(16) __nv_bfloat16 sb_l[128 * GAP];

    const int tid  = threadIdx.x;
    const int lane = tid & 31;
    const int wrp  = tid >> 5;
    const int row0 = blockIdx.x * 128;

    const int m0 = (wrp & 1) * 64;
    const int n0 = (wrp >> 1) * 32;
    const int rsel = lane >> 3, rin = lane & 7;

    const uint32_t sah = smem_u32(sa_h), sal = smem_u32(sa_l);
    const uint32_t sbh = smem_u32(sb_h), sbl = smem_u32(sb_l);

    float acc[4][4][4];
#pragma unroll
    for (int mt = 0; mt < 4; ++mt)
#pragma unroll
        for (int nt = 0; nt < 4; ++nt)
#pragma unroll
            for (int i = 0; i < 4; ++i) acc[mt][nt][i] = 0.0f;

    for (int kt = 0; kt < 4; ++kt) {
#pragma unroll
        for (int i = 0; i < 4; ++i) {
            int idx = tid + i * 256;
            int r = idx >> 3, q = idx & 7;
            int rg = row0 + r; if (rg > n - 1) rg = n - 1;
            float4 v = *(const float4*)&feat[(size_t)rg * DIN + kt * 32 + q * 4];
            uint2 hp, lp;
            split4(v, hp, lp);
            *(uint2*)&sa_h[r * GAP + q * 4] = hp;
            *(uint2*)&sa_l[r * GAP + q * 4] = lp;
        }
#pragma unroll
        for (int i = 0; i < 2; ++i) {
            int idx = tid + i * 256;
            int r = idx >> 2, q = idx & 3;
            *(uint4*)&sb_h[r * GAP + q * 8] =
                *(const uint4*)&g_wThi[r * 128 + kt * 32 + q * 8];
            *(uint4*)&sb_l[r * GAP + q * 8] =
                *(const uint4*)&g_wTlo[r * 128 + kt * 32 + q * 8];
        }
        __syncthreads();

#pragma unroll
        for (int kc = 0; kc < 2; ++kc) {
            const uint32_t kadd = kc * 32;
            uint32_t bh[8], bl[8];
#pragma unroll
            for (int h = 0; h < 2; ++h) {
                uint32_t boff = (uint32_t)((n0 + h * 16 + (rsel >> 1) * 8 + rin) * GAP
                                           + (rsel & 1) * 8) * 2 + kadd;
                ldmatrix_x4(&bh[h * 4], sbh + boff);
                ldmatrix_x4(&bl[h * 4], sbl + boff);
            }
#pragma unroll
            for (int mt = 0; mt < 4; ++mt) {
                uint32_t aoff = (uint32_t)((m0 + mt * 16 + (rsel & 1) * 8 + rin) * GAP
                                           + (rsel >> 1) * 8) * 2 + kadd;
                uint32_t ah[4], al[4];
                ldmatrix_x4(ah, sah + aoff);
                ldmatrix_x4(al, sal + aoff);
#pragma unroll
                for (int nt = 0; nt < 4; ++nt) {
                    mma_bf16(acc[mt][nt], ah, &bh[nt * 2]);
                    mma_bf16(acc[mt][nt], ah, &bl[nt * 2]);
                    mma_bf16(acc[mt][nt], al, &bh[nt * 2]);
                }
            }
        }
        __syncthreads();
    }

#pragma unroll
    for (int mt = 0; mt < 4; ++mt) {
        int ra = row0 + m0 + mt * 16 + (lane >> 2);
#pragma unroll
        for (int nt = 0; nt < 4; ++nt) {
            int cb = n0 + nt * 8 + 2 * (lane & 3);
            *(float2*)&g_x[(size_t)ra * DOUT + cb] =
                make_float2(acc[mt][nt][0], acc[mt][nt][1]);
            *(float2*)&g_x[(size_t)(ra + 8) * DOUT + cb] =
                make_float2(acc[mt][nt][2], acc[mt][nt][3]);
        }
    }
}

// ---------------------------------------------------------------------------
// Kernel B: top-k, 3-pass Gram with IN-FRAGMENT distance epilogue, softmax, agg
// 1 CTA per node, 128 threads (4 warps, 2x2 over the 32x32 Gram)
// ---------------------------------------------------------------------------
#define BPITCH 136

__global__ __launch_bounds__(128) void node_kernel(const float* __restrict__ ew,
                                                   const int*   __restrict__ nbr,
                                                   const float* __restrict__ bias,
                                                   float*       __restrict__ out,
                                                   int n)
{
    __shared__ __align__(16) __nv_bfloat16 xhi[32 * BPITCH];
    __shared__ __align__(16) __nv_bfloat16 xlo[32 * BPITCH];
    __shared__ float sw49[52];
    __shared__ int   sid49[52];
    __shared__ float selw[32];
    __shared__ int   selid[32];
    __shared__ float ssq[32];
    __shared__ float sdA[32];    // dist partial, cols 0..15
    __shared__ float sdB[32];    // dist partial, cols 16..31
    __shared__ float srel[32];

    const int node = blockIdx.x;
    const int tid  = threadIdx.x;
    const int lane = tid & 31;
    const int wrp  = tid >> 5;

    // --- load 48 edges + self-loop ---
    if (tid < DEG) {
        sw49[tid]  = ew[(size_t)node * DEG + tid];
        sid49[tid] = nbr[(size_t)node * DEG + tid];
    } else if (tid == DEG) {
        sw49[DEG]  = 1.0f;
        sid49[DEG] = node;
    }
    __syncthreads();

    // --- top-32 of 49 (stable rank = lax.top_k tie-break) ---
    if (tid < DEG + 1) {
        float v = sw49[tid];
        int rank = 0;
#pragma unroll
        for (int j = 0; j < DEG + 1; ++j) {
            float wj = sw49[j];
            rank += (wj > v) || (wj == v && j < tid);
        }
        if (rank < KSEL) {
            selw[rank]  = v;
            selid[rank] = sid49[tid];
        }
    }
    __syncthreads();

    // --- gather fp32 rows (coalesced), truncation-split to bf16 hi/lo ---
    {
        const int r0 = wrp * 8;
        const int c0 = lane * 4;
#pragma unroll
        for (int r = 0; r < 8; ++r) {
            const int row = r0 + r;
            const int id  = selid[row];
            float4 v = *(const float4*)&g_x[(size_t)id * DOUT + c0];
            uint2 hp, lp;
            split4(v, hp, lp);
            *(uint2*)&xhi[row * BPITCH + c0] = hp;
            *(uint2*)&xlo[row * BPITCH + c0] = lp;
        }
    }
    __syncthreads();

    // --- Gram 3-pass (hh + hl + lh), accumulated into final c-fragments ---
    const int m0 = (wrp & 1) * 16;
    const int n0 = (wrp >> 1) * 16;
    float c0f[4] = {0.f, 0.f, 0.f, 0.f};
    float c1f[4] = {0.f, 0.f, 0.f, 0.f};
    {
        const int rsel = lane >> 3, rin = lane & 7;
        const uint32_t a_off = (uint32_t)((m0 + (rsel & 1) * 8 + rin) * BPITCH
                                          + ((rsel >> 1) * 8)) * 2;
        const uint32_t b_off = (uint32_t)((n0 + (rsel >> 1) * 8 + rin) * BPITCH
                                          + ((rsel & 1) * 8)) * 2;
        const uint32_t hbase = smem_u32(xhi);
        const uint32_t lbase = smem_u32(xlo);

#pragma unroll
        for (int kc = 0; kc < 8; ++kc) {
            const uint32_t kadd = (uint32_t)(kc * 32);
            uint32_t ah[4], al[4], bh[4], bl[4];
            ldmatrix_x4(ah, hbase + a_off + kadd);
            ldmatrix_x4(al, lbase + a_off + kadd);
            ldmatrix_x4(bh, hbase + b_off + kadd);
            ldmatrix_x4(bl, lbase + b_off + kadd);

            mma_bf16(c0f, ah, &bh[0]);
            mma_bf16(c0f, ah, &bl[0]);
            mma_bf16(c0f, al, &bh[0]);
            mma_bf16(c1f, ah, &bh[2]);
            mma_bf16(c1f, ah, &bl[2]);
            mma_bf16(c1f, al, &bh[2]);
        }
    }

    // --- diagonal -> ssq (fragment owners of (a,a)) ---
    const int p = lane >> 2;          // row within 8
    const int q = lane & 3;           // col pair index
    if (m0 == n0) {
        if (p == 2 * q) {
            ssq[m0 + p]     = c0f[0];   // (p, 2q)
            ssq[m0 + p + 8] = c1f[2];   // (p+8, 8+2q)
        }
        if (p == 2 * q + 1) {
            ssq[m0 + p]     = c0f[1];   // (p, 2q+1)
            ssq[m0 + p + 8] = c1f[3];   // (p+8, 8+2q+1)
        }
    }
    __syncthreads();

    // --- in-fragment weighted medoid distance partials ---
    {
        const int b0 = n0 + 2 * q, b1 = b0 + 1, b2 = b0 + 8, b3 = b2 + 1;
        const float w0 = selw[b0], w1 = selw[b1], w2 = selw[b2], w3 = selw[b3];
        const float s0 = ssq[b0], s1 = ssq[b1], s2 = ssq[b2], s3 = ssq[b3];
        const float sqa  = ssq[m0 + p];
        const float sqa8 = ssq[m0 + p + 8];

        float d;
        float part = 0.f, part8 = 0.f;
        d = sqa  + s0 - 2.f * c0f[0]; part  = fmaf(w0, (d > 0.f) ? sqrtf(d) : 0.f, part);
        d = sqa  + s1 - 2.f * c0f[1]; part  = fmaf(w1, (d > 0.f) ? sqrtf(d) : 0.f, part);
        d = sqa  + s2 - 2.f * c1f[0]; part  = fmaf(w2, (d > 0.f) ? sqrtf(d) : 0.f, part);
        d = sqa  + s3 - 2.f * c1f[1]; part  = fmaf(w3, (d > 0.f) ? sqrtf(d) : 0.f, part);
        d = sqa8 + s0 - 2.f * c0f[2]; part8 = fmaf(w0, (d > 0.f) ? sqrtf(d) : 0.f, part8);
        d = sqa8 + s1 - 2.f * c0f[3]; part8 = fmaf(w1, (d > 0.f) ? sqrtf(d) : 0.f, part8);
        d = sqa8 + s2 - 2.f * c1f[2]; part8 = fmaf(w2, (d > 0.f) ? sqrtf(d) : 0.f, part8);
        d = sqa8 + s3 - 2.f * c1f[3]; part8 = fmaf(w3, (d > 0.f) ? sqrtf(d) : 0.f, part8);

        // quad reduce over q (lanes 4p..4p+3)
        part  += __shfl_down_sync(0xffffffffu, part, 2);
        part  += __shfl_down_sync(0xffffffffu, part, 1);
        part8 += __shfl_down_sync(0xffffffffu, part8, 2);
        part8 += __shfl_down_sync(0xffffffffu, part8, 1);

        if (q == 0) {
            float* dst = (n0 == 0) ? sdA : sdB;
            dst[m0 + p]     = part;
            dst[m0 + p + 8] = part8;
        }
    }
    __syncthreads();

    // --- softmax(-dist) * tw, renormalized (warp 0) ---
    if (tid < 32) {
        float v = sdA[tid] + sdB[tid];
        float m = v;
#pragma unroll
        for (int off = 16; off; off >>= 1)
            m = fminf(m, __shfl_xor_sync(0xffffffffu, m, off));
        float r = expf(m - v) * selw[tid];
        float s = r;
#pragma unroll
        for (int off = 16; off; off >>= 1)
            s += __shfl_xor_sync(0xffffffffu, s, off);
        srel[tid] = r / s;
    }
    __syncthreads();

    // --- out[d] = bias[d] + sum_k rel[k] * x[sel[k]][d]  (L1-hot re-gather) ---
    {
        float acc = bias[tid];
#pragma unroll
        for (int k = 0; k < 32; ++k)
            acc = fmaf(srel[k], g_x[(size_t)selid[k] * DOUT + tid], acc);
        out[(size_t)node * DOUT + tid] = acc;
    }
}

// ---------------------------------------------------------------------------
// Launch
// ---------------------------------------------------------------------------
extern "C" void kernel_launch(void* const* d_in, const int* in_sizes, int n_in,
                              void* d_out, int out_size)
{
    const float* feat   = (const float*)d_in[0];
    const float* ew     = (const float*)d_in[1];
    const float* weight = (const float*)d_in[2];
    const float* bias   = (const float*)d_in[3];
    const int*   nbr    = (const int*)  d_in[4];
    float*       out    = (float*)d_out;

    int n = in_sizes[0] / DIN;

    wsplit_kernel<<<64, 256>>>(weight);
    gemm_kernel<<<(n + 127) / 128, 256>>>(feat, n);
    node_kernel<<<n, 128>>>(ew, nbr, bias, out, n);
}

// round 9
// speedup vs baseline: 1.3654x; 1.0841x over previous
#include <cuda_runtime.h>
#include <cuda_bf16.h>
#include <cstdint>

// Problem constants
#define DIN   128
#define DOUT  128
#define DEG   48
#define KSEL  32
#define NPAD  50048

__device__ __nv_bfloat16 g_xhi[(size_t)NPAD * DOUT];   // trunc hi of x
__device__ __nv_bfloat16 g_xlo[(size_t)NPAD * DOUT];   // rn residual lo
__device__ __nv_bfloat16 g_wThi[128 * 128];            // W^T hi, [n][k]
__device__ __nv_bfloat16 g_wTlo[128 * 128];            // W^T lo, [n][k]

// ---------------------------------------------------------------------------
// Common helpers
// ---------------------------------------------------------------------------
__device__ __forceinline__ uint32_t smem_u32(const void* p) {
    uint32_t a;
    asm("{ .reg .u64 t; cvta.to.shared.u64 t, %1; cvt.u32.u64 %0, t; }" : "=r"(a) : "l"(p));
    return a;
}

__device__ __forceinline__ void ldmatrix_x4(uint32_t* r, uint32_t addr) {
    asm volatile("ldmatrix.sync.aligned.m8n8.x4.shared.b16 {%0,%1,%2,%3}, [%4];"
                 : "=r"(r[0]), "=r"(r[1]), "=r"(r[2]), "=r"(r[3]) : "r"(addr));
}

__device__ __forceinline__ void ldmatrix_x4_trans(uint32_t* r, uint32_t addr) {
    asm volatile("ldmatrix.sync.aligned.m8n8.x4.trans.shared.b16 {%0,%1,%2,%3}, [%4];"
                 : "=r"(r[0]), "=r"(r[1]), "=r"(r[2]), "=r"(r[3]) : "r"(addr));
}

__device__ __forceinline__ void mma_bf16(float* c, const uint32_t* a, const uint32_t* b) {
    asm volatile(
        "mma.sync.aligned.m16n8k16.row.col.f32.bf16.bf16.f32 "
        "{%0,%1,%2,%3}, {%4,%5,%6,%7}, {%8,%9}, {%0,%1,%2,%3};"
        : "+f"(c[0]), "+f"(c[1]), "+f"(c[2]), "+f"(c[3])
        : "r"(a[0]), "r"(a[1]), "r"(a[2]), "r"(a[3]), "r"(b[0]), "r"(b[1]));
}

// Truncation split: hi = top-16 bits of fp32, lo = rn-bf16 of (x - hi).
__device__ __forceinline__ void split4(float4 v, uint2& hp, uint2& lp) {
    uint32_t ax = __float_as_uint(v.x), ay = __float_as_uint(v.y);
    uint32_t az = __float_as_uint(v.z), aw = __float_as_uint(v.w);
    hp.x = __byte_perm(ax, ay, 0x7632);
    hp.y = __byte_perm(az, aw, 0x7632);
    float lx = v.x - __uint_as_float(ax & 0xffff0000u);
    float ly = v.y - __uint_as_float(ay & 0xffff0000u);
    float lz = v.z - __uint_as_float(az & 0xffff0000u);
    float lw = v.w - __uint_as_float(aw & 0xffff0000u);
    asm("cvt.rn.bf16x2.f32 %0, %1, %2;" : "=r"(lp.x) : "f"(ly), "f"(lx));
    asm("cvt.rn.bf16x2.f32 %0, %1, %2;" : "=r"(lp.y) : "f"(lw), "f"(lz));
}

__device__ __forceinline__ void split2(float x, float y, uint32_t& hp, uint32_t& lp) {
    uint32_t ax = __float_as_uint(x), ay = __float_as_uint(y);
    hp = __byte_perm(ax, ay, 0x7632);
    float lx = x - __uint_as_float(ax & 0xffff0000u);
    float ly = y - __uint_as_float(ay & 0xffff0000u);
    asm("cvt.rn.bf16x2.f32 %0, %1, %2;" : "=r"(lp) : "f"(ly), "f"(lx));
}

// ---------------------------------------------------------------------------
// Kernel 0: transpose + split W -> g_wThi/g_wTlo  ([n][k] bf16)
// ---------------------------------------------------------------------------
__global__ __launch_bounds__(256) void wsplit_kernel(const float* __restrict__ W)
{
    int idx = blockIdx.x * 256 + threadIdx.x;
    int k = idx >> 7, nn = idx & 127;
    float v = W[k * 128 + nn];
    uint32_t b = __float_as_uint(v);
    uint32_t hbits = b & 0xffff0000u;
    float lo = v - __uint_as_float(hbits);
    g_wThi[nn * 128 + k] = __ushort_as_bfloat16((unsigned short)(hbits >> 16));
    g_wTlo[nn * 128 + k] = __float2bfloat16_rn(lo);
}

// ---------------------------------------------------------------------------
// Kernel A: x = feat @ W via bf16 3-pass mma.sync; epilogue stores hi/lo only
// ---------------------------------------------------------------------------
#define GAP 40   // bf16 smem pitch (80 B), ldmatrix conflict-free

__global__ __launch_bounds__(256) void gemm_kernel(const float* __restrict__ feat,
                                                   int n)
{
    __shared__ __align__(16) __nv_bfloat16 sa_h[128 * GAP];
    __shared__ __align__(16) __nv_bfloat16 sa_l[128 * GAP];
    __shared__ __align__(16) __nv_bfloat16 sb_h[128 * GAP];
    __shared__ __align__(16) __nv_bfloat16 sb_l[128 * GAP];

    const int tid  = threadIdx.x;
    const int lane = tid & 31;
    const int wrp  = tid >> 5;
    const int row0 = blockIdx.x * 128;

    const int m0 = (wrp & 1) * 64;
    const int n0 = (wrp >> 1) * 32;
    const int rsel = lane >> 3, rin = lane & 7;

    const uint32_t sah = smem_u32(sa_h), sal = smem_u32(sa_l);
    const uint32_t sbh = smem_u32(sb_h), sbl = smem_u32(sb_l);

    float acc[4][4][4];
#pragma unroll
    for (int mt = 0; mt < 4; ++mt)
#pragma unroll
        for (int nt = 0; nt < 4; ++nt)
#pragma unroll
            for (int i = 0; i < 4; ++i) acc[mt][nt][i] = 0.0f;

    for (int kt = 0; kt < 4; ++kt) {
#pragma unroll
        for (int i = 0; i < 4; ++i) {
            int idx = tid + i * 256;
            int r = idx >> 3, q = idx & 7;
            int rg = row0 + r; if (rg > n - 1) rg = n - 1;
            float4 v = *(const float4*)&feat[(size_t)rg * DIN + kt * 32 + q * 4];
            uint2 hp, lp;
            split4(v, hp, lp);
            *(uint2*)&sa_h[r * GAP + q * 4] = hp;
            *(uint2*)&sa_l[r * GAP + q * 4] = lp;
        }
#pragma unroll
        for (int i = 0; i < 2; ++i) {
            int idx = tid + i * 256;
            int r = idx >> 2, q = idx & 3;
            *(uint4*)&sb_h[r * GAP + q * 8] =
                *(const uint4*)&g_wThi[r * 128 + kt * 32 + q * 8];
            *(uint4*)&sb_l[r * GAP + q * 8] =
                *(const uint4*)&g_wTlo[r * 128 + kt * 32 + q * 8];
        }
        __syncthreads();

#pragma unroll
        for (int kc = 0; kc < 2; ++kc) {
            const uint32_t kadd = kc * 32;
            uint32_t bh[8], bl[8];
#pragma unroll
            for (int h = 0; h < 2; ++h) {
                uint32_t boff = (uint32_t)((n0 + h * 16 + (rsel >> 1) * 8 + rin) * GAP
                                           + (rsel & 1) * 8) * 2 + kadd;
                ldmatrix_x4(&bh[h * 4], sbh + boff);
                ldmatrix_x4(&bl[h * 4], sbl + boff);
            }
#pragma unroll
            for (int mt = 0; mt < 4; ++mt) {
                uint32_t aoff = (uint32_t)((m0 + mt * 16 + (rsel & 1) * 8 + rin) * GAP
                                           + (rsel >> 1) * 8) * 2 + kadd;
                uint32_t ah[4], al[4];
                ldmatrix_x4(ah, sah + aoff);
                ldmatrix_x4(al, sal + aoff);
#pragma unroll
                for (int nt = 0; nt < 4; ++nt) {
                    mma_bf16(acc[mt][nt], ah, &bh[nt * 2]);
                    mma_bf16(acc[mt][nt], ah, &bl[nt * 2]);
                    mma_bf16(acc[mt][nt], al, &bh[nt * 2]);
                }
            }
        }
        __syncthreads();
    }

    // epilogue: trunc-split and store hi/lo (identical bits to in-kernel split)
#pragma unroll
    for (int mt = 0; mt < 4; ++mt) {
        int ra = row0 + m0 + mt * 16 + (lane >> 2);
#pragma unroll
        for (int nt = 0; nt < 4; ++nt) {
            int cb = n0 + nt * 8 + 2 * (lane & 3);
            uint32_t hp, lp;
            split2(acc[mt][nt][0], acc[mt][nt][1], hp, lp);
            *(uint32_t*)&g_xhi[(size_t)ra * DOUT + cb] = hp;
            *(uint32_t*)&g_xlo[(size_t)ra * DOUT + cb] = lp;
            split2(acc[mt][nt][2], acc[mt][nt][3], hp, lp);
            *(uint32_t*)&g_xhi[(size_t)(ra + 8) * DOUT + cb] = hp;
            *(uint32_t*)&g_xlo[(size_t)(ra + 8) * DOUT + cb] = lp;
        }
    }
}

// ---------------------------------------------------------------------------
// Kernel B: top-k, 3-pass Gram + in-fragment distances, softmax, mma agg
// 1 CTA per node, 128 threads (4 warps)
// ---------------------------------------------------------------------------
#define BPITCH 136

__global__ __launch_bounds__(128) void node_kernel(const float* __restrict__ ew,
                                                   const int*   __restrict__ nbr,
                                                   const float* __restrict__ bias,
                                                   float*       __restrict__ out,
                                                   int n)
{
    __shared__ __align__(16) __nv_bfloat16 xhi[32 * BPITCH];
    __shared__ __align__(16) __nv_bfloat16 xlo[32 * BPITCH];
    __shared__ float sw49[52];
    __shared__ int   sid49[52];
    __shared__ float selw[32];
    __shared__ int   selid[32];
    __shared__ float ssq[32];
    __shared__ float sdA[32];
    __shared__ float sdB[32];
    __shared__ __align__(4) unsigned short srelh[32];   // rel trunc hi bf16
    __shared__ __align__(4) unsigned short srell[32];   // rel residual lo bf16
    __shared__ __align__(16) float sout[128];

    const int node = blockIdx.x;
    const int tid  = threadIdx.x;
    const int lane = tid & 31;
    const int wrp  = tid >> 5;

    // --- load 48 edges + self-loop ---
    if (tid < DEG) {
        sw49[tid]  = ew[(size_t)node * DEG + tid];
        sid49[tid] = nbr[(size_t)node * DEG + tid];
    } else if (tid == DEG) {
        sw49[DEG]  = 1.0f;
        sid49[DEG] = node;
    }
    __syncthreads();

    // --- top-32 of 49 (stable rank = lax.top_k tie-break) ---
    if (tid < DEG + 1) {
        float v = sw49[tid];
        int rank = 0;
#pragma unroll
        for (int j = 0; j < DEG + 1; ++j) {
            float wj = sw49[j];
            rank += (wj > v) || (wj == v && j < tid);
        }
        if (rank < KSEL) {
            selw[rank]  = v;
            selid[rank] = sid49[tid];
        }
    }
    __syncthreads();

    // --- gather pre-split bf16 rows (coalesced, no split work) ---
    {
        const int r0 = wrp * 8;
        const int c0 = lane * 4;
#pragma unroll
        for (int r = 0; r < 8; ++r) {
            const int row = r0 + r;
            const size_t base = (size_t)selid[row] * DOUT + c0;
            *(uint2*)&xhi[row * BPITCH + c0] = *(const uint2*)&g_xhi[base];
            *(uint2*)&xlo[row * BPITCH + c0] = *(const uint2*)&g_xlo[base];
        }
    }
    __syncthreads();

    // --- Gram 3-pass (hh + hl + lh), final values in c-fragments ---
    const int m0 = (wrp & 1) * 16;
    const int n0 = (wrp >> 1) * 16;
    const uint32_t hbase = smem_u32(xhi);
    const uint32_t lbase = smem_u32(xlo);
    float c0f[4] = {0.f, 0.f, 0.f, 0.f};
    float c1f[4] = {0.f, 0.f, 0.f, 0.f};
    {
        const int rsel = lane >> 3, rin = lane & 7;
        const uint32_t a_off = (uint32_t)((m0 + (rsel & 1) * 8 + rin) * BPITCH
                                          + ((rsel >> 1) * 8)) * 2;
        const uint32_t b_off = (uint32_t)((n0 + (rsel >> 1) * 8 + rin) * BPITCH
                                          + ((rsel & 1) * 8)) * 2;

#pragma unroll
        for (int kc = 0; kc < 8; ++kc) {
            const uint32_t kadd = (uint32_t)(kc * 32);
            uint32_t ah[4], al[4], bh[4], bl[4];
            ldmatrix_x4(ah, hbase + a_off + kadd);
            ldmatrix_x4(al, lbase + a_off + kadd);
            ldmatrix_x4(bh, hbase + b_off + kadd);
            ldmatrix_x4(bl, lbase + b_off + kadd);

            mma_bf16(c0f, ah, &bh[0]);
            mma_bf16(c0f, ah, &bl[0]);
            mma_bf16(c0f, al, &bh[0]);
            mma_bf16(c1f, ah, &bh[2]);
            mma_bf16(c1f, ah, &bl[2]);
            mma_bf16(c1f, al, &bh[2]);
        }
    }

    // --- diagonal -> ssq ---
    const int p = lane >> 2;
    const int q = lane & 3;
    if (m0 == n0) {
        if (p == 2 * q) {
            ssq[m0 + p]     = c0f[0];
            ssq[m0 + p + 8] = c1f[2];
        }
        if (p == 2 * q + 1) {
            ssq[m0 + p]     = c0f[1];
            ssq[m0 + p + 8] = c1f[3];
        }
    }
    __syncthreads();

    // --- in-fragment weighted medoid distance partials ---
    {
        const int b0 = n0 + 2 * q, b1 = b0 + 1, b2 = b0 + 8, b3 = b2 + 1;
        const float w0 = selw[b0], w1 = selw[b1], w2 = selw[b2], w3 = selw[b3];
        const float s0 = ssq[b0], s1 = ssq[b1], s2 = ssq[b2], s3 = ssq[b3];
        const float sqa  = ssq[m0 + p];
        const float sqa8 = ssq[m0 + p + 8];

        float d;
        float part = 0.f, part8 = 0.f;
        d = sqa  + s0 - 2.f * c0f[0]; part  = fmaf(w0, (d > 0.f) ? sqrtf(d) : 0.f, part);
        d = sqa  + s1 - 2.f * c0f[1]; part  = fmaf(w1, (d > 0.f) ? sqrtf(d) : 0.f, part);
        d = sqa  + s2 - 2.f * c1f[0]; part  = fmaf(w2, (d > 0.f) ? sqrtf(d) : 0.f, part);
        d = sqa  + s3 - 2.f * c1f[1]; part  = fmaf(w3, (d > 0.f) ? sqrtf(d) : 0.f, part);
        d = sqa8 + s0 - 2.f * c0f[2]; part8 = fmaf(w0, (d > 0.f) ? sqrtf(d) : 0.f, part8);
        d = sqa8 + s1 - 2.f * c0f[3]; part8 = fmaf(w1, (d > 0.f) ? sqrtf(d) : 0.f, part8);
        d = sqa8 + s2 - 2.f * c1f[2]; part8 = fmaf(w2, (d > 0.f) ? sqrtf(d) : 0.f, part8);
        d = sqa8 + s3 - 2.f * c1f[3]; part8 = fmaf(w3, (d > 0.f) ? sqrtf(d) : 0.f, part8);

        part  += __shfl_down_sync(0xffffffffu, part, 2);
        part  += __shfl_down_sync(0xffffffffu, part, 1);
        part8 += __shfl_down_sync(0xffffffffu, part8, 2);
        part8 += __shfl_down_sync(0xffffffffu, part8, 1);

        if (q == 0) {
            float* dst = (n0 == 0) ? sdA : sdB;
            dst[m0 + p]     = part;
            dst[m0 + p + 8] = part8;
        }
    }
    __syncthreads();

    // --- softmax(-dist) * tw, renormalized; emit rel as trunc hi + rn lo ---
    if (tid < 32) {
        float v = sdA[tid] + sdB[tid];
        float m = v;
#pragma unroll
        for (int off = 16; off; off >>= 1)
            m = fminf(m, __shfl_xor_sync(0xffffffffu, m, off));
        float r = expf(m - v) * selw[tid];
        float s = r;
#pragma unroll
        for (int off = 16; off; off >>= 1)
            s += __shfl_xor_sync(0xffffffffu, s, off);
        float rr = r / s;
        uint32_t bits = __float_as_uint(rr);
        srelh[tid] = (unsigned short)(bits >> 16);
        float rl = rr - __uint_as_float(bits & 0xffff0000u);
        srell[tid] = __bfloat16_as_ushort(__float2bfloat16_rn(rl));
    }
    __syncthreads();

    // --- aggregation via mma: out = rel^T @ X; warp w covers cols 32w..32w+31 ---
    {
        const uint32_t* relh32 = (const uint32_t*)srelh;
        const uint32_t* rell32 = (const uint32_t*)srell;
        const int n0w = wrp * 32;
        const int g = lane >> 3, rr = lane & 7;

        float cagg[4][4];
#pragma unroll
        for (int i = 0; i < 4; ++i)
#pragma unroll
            for (int j = 0; j < 4; ++j) cagg[i][j] = 0.f;

#pragma unroll
        for (int kc = 0; kc < 2; ++kc) {
            // A-frags: row 0 = rel chunk kc*16..+15 (rows 1..15 junk, unread)
            uint32_t ah[4], al[4];
            ah[0] = relh32[kc * 8 + q];     ah[1] = ah[0];
            ah[2] = relh32[kc * 8 + 4 + q]; ah[3] = ah[2];
            al[0] = rell32[kc * 8 + q];     al[1] = al[0];
            al[2] = rell32[kc * 8 + 4 + q]; al[3] = al[2];

            // B-frags via trans ldmatrix: source rows = k, cols = n
#pragma unroll
            for (int t = 0; t < 2; ++t) {
                const int nA = n0w + t * 16;
                uint32_t addr_off = (uint32_t)(((kc * 16 + (g & 1) * 8 + rr) * BPITCH
                                               + nA + (g >> 1) * 8) * 2);
                uint32_t bh[4], bl[4];
                ldmatrix_x4_trans(bh, hbase + addr_off);
                ldmatrix_x4_trans(bl, lbase + addr_off);

                // tile 2t   (cols nA..nA+7):  regs {bh[0],bh[1]}
                mma_bf16(cagg[2 * t], ah, &bh[0]);
                mma_bf16(cagg[2 * t], ah, &bl[0]);
                mma_bf16(cagg[2 * t], al, &bh[0]);
                // tile 2t+1 (cols nA+8..+15): regs {bh[2],bh[3]}
                mma_bf16(cagg[2 * t + 1], ah, &bh[2]);
                mma_bf16(cagg[2 * t + 1], ah, &bl[2]);
                mma_bf16(cagg[2 * t + 1], al, &bh[2]);
            }
        }

        // D row 0 lives in lanes 0..3 (c0 = col 2q, c1 = col 2q+1)
        if (lane < 4) {
#pragma unroll
            for (int i = 0; i < 4; ++i)
                *(float2*)&sout[n0w + i * 8 + 2 * lane] =
                    make_float2(cagg[i][0], cagg[i][1]);
        }
    }
    __syncthreads();

    out[(size_t)node * DOUT + tid] = sout[tid] + bias[tid];
}

// ---------------------------------------------------------------------------
// Launch
// ---------------------------------------------------------------------------
extern "C" void kernel_launch(void* const* d_in, const int* in_sizes, int n_in,
                              void* d_out, int out_size)
{
    const float* feat   = (const float*)d_in[0];
    const float* ew     = (const float*)d_in[1];
    const float* weight = (const float*)d_in[2];
    const float* bias   = (const float*)d_in[3];
    const int*   nbr    = (const int*)  d_in[4];
    float*       out    = (float*)d_out;

    int n = in_sizes[0] / DIN;

    wsplit_kernel<<<64, 256>>>(weight);
    gemm_kernel<<<(n + 127) / 128, 256>>>(feat, n);
    node_kernel<<<n, 128>>>(ew, nbr, bias, out, n);
}

// round 10
// speedup vs baseline: 1.4835x; 1.0865x over previous
#include <cuda_runtime.h>
#include <cuda_bf16.h>
#include <cstdint>

// Problem constants
#define DIN   128
#define DOUT  128
#define DEG   48
#define KSEL  32
#define NPAD  50048

__device__ __nv_bfloat16 g_xhi[(size_t)NPAD * DOUT];   // trunc hi of x
__device__ __nv_bfloat16 g_xlo[(size_t)NPAD * DOUT];   // rn residual lo
__device__ __nv_bfloat16 g_wThi[128 * 128];            // W^T hi, [n][k]
__device__ __nv_bfloat16 g_wTlo[128 * 128];            // W^T lo, [n][k]

// ---------------------------------------------------------------------------
// Common helpers
// ---------------------------------------------------------------------------
__device__ __forceinline__ uint32_t smem_u32(const void* p) {
    uint32_t a;
    asm("{ .reg .u64 t; cvta.to.shared.u64 t, %1; cvt.u32.u64 %0, t; }" : "=r"(a) : "l"(p));
    return a;
}

__device__ __forceinline__ void ldmatrix_x4(uint32_t* r, uint32_t addr) {
    asm volatile("ldmatrix.sync.aligned.m8n8.x4.shared.b16 {%0,%1,%2,%3}, [%4];"
                 : "=r"(r[0]), "=r"(r[1]), "=r"(r[2]), "=r"(r[3]) : "r"(addr));
}

__device__ __forceinline__ void ldmatrix_x4_trans(uint32_t* r, uint32_t addr) {
    asm volatile("ldmatrix.sync.aligned.m8n8.x4.trans.shared.b16 {%0,%1,%2,%3}, [%4];"
                 : "=r"(r[0]), "=r"(r[1]), "=r"(r[2]), "=r"(r[3]) : "r"(addr));
}

__device__ __forceinline__ void mma_bf16(float* c, const uint32_t* a, const uint32_t* b) {
    asm volatile(
        "mma.sync.aligned.m16n8k16.row.col.f32.bf16.bf16.f32 "
        "{%0,%1,%2,%3}, {%4,%5,%6,%7}, {%8,%9}, {%0,%1,%2,%3};"
        : "+f"(c[0]), "+f"(c[1]), "+f"(c[2]), "+f"(c[3])
        : "r"(a[0]), "r"(a[1]), "r"(a[2]), "r"(a[3]), "r"(b[0]), "r"(b[1]));
}

// Truncation split: hi = top-16 bits of fp32, lo = rn-bf16 of (x - hi).
__device__ __forceinline__ void split4(float4 v, uint2& hp, uint2& lp) {
    uint32_t ax = __float_as_uint(v.x), ay = __float_as_uint(v.y);
    uint32_t az = __float_as_uint(v.z), aw = __float_as_uint(v.w);
    hp.x = __byte_perm(ax, ay, 0x7632);
    hp.y = __byte_perm(az, aw, 0x7632);
    float lx = v.x - __uint_as_float(ax & 0xffff0000u);
    float ly = v.y - __uint_as_float(ay & 0xffff0000u);
    float lz = v.z - __uint_as_float(az & 0xffff0000u);
    float lw = v.w - __uint_as_float(aw & 0xffff0000u);
    asm("cvt.rn.bf16x2.f32 %0, %1, %2;" : "=r"(lp.x) : "f"(ly), "f"(lx));
    asm("cvt.rn.bf16x2.f32 %0, %1, %2;" : "=r"(lp.y) : "f"(lw), "f"(lz));
}

__device__ __forceinline__ void split2(float x, float y, uint32_t& hp, uint32_t& lp) {
    uint32_t ax = __float_as_uint(x), ay = __float_as_uint(y);
    hp = __byte_perm(ax, ay, 0x7632);
    float lx = x - __uint_as_float(ax & 0xffff0000u);
    float ly = y - __uint_as_float(ay & 0xffff0000u);
    asm("cvt.rn.bf16x2.f32 %0, %1, %2;" : "=r"(lp) : "f"(ly), "f"(lx));
}

// ---------------------------------------------------------------------------
// Kernel 0: transpose + split W -> g_wThi/g_wTlo  ([n][k] bf16)
// ---------------------------------------------------------------------------
__global__ __launch_bounds__(256) void wsplit_kernel(const float* __restrict__ W)
{
    int idx = blockIdx.x * 256 + threadIdx.x;
    int k = idx >> 7, nn = idx & 127;
    float v = W[k * 128 + nn];
    uint32_t b = __float_as_uint(v);
    uint32_t hbits = b & 0xffff0000u;
    float lo = v - __uint_as_float(hbits);
    g_wThi[nn * 128 + k] = __ushort_as_bfloat16((unsigned short)(hbits >> 16));
    g_wTlo[nn * 128 + k] = __float2bfloat16_rn(lo);
}

// ---------------------------------------------------------------------------
// Kernel A: x = feat @ W via bf16 3-pass mma.sync; epilogue stores hi/lo only
// ---------------------------------------------------------------------------
#define GAP 40   // bf16 smem pitch (80 B), ldmatrix conflict-free

__global__ __launch_bounds__(256) void gemm_kernel(const float* __restrict__ feat,
                                                   int n)
{
    __shared__ __align__(16) __nv_bfloat16 sa_h[128 * GAP];
    __shared__ __align__(16) __nv_bfloat16 sa_l[128 * GAP];
    __shared__ __align__(16) __nv_bfloat16 sb_h[128 * GAP];
    __shared__ __align__(16) __nv_bfloat16 sb_l[128 * GAP];

    const int tid  = threadIdx.x;
    const int lane = tid & 31;
    const int wrp  = tid >> 5;
    const int row0 = blockIdx.x * 128;

    const int m0 = (wrp & 1) * 64;
    const int n0 = (wrp >> 1) * 32;
    const int rsel = lane >> 3, rin = lane & 7;

    const uint32_t sah = smem_u32(sa_h), sal = smem_u32(sa_l);
    const uint32_t sbh = smem_u32(sb_h), sbl = smem_u32(sb_l);

    float acc[4][4][4];
#pragma unroll
    for (int mt = 0; mt < 4; ++mt)
#pragma unroll
        for (int nt = 0; nt < 4; ++nt)
#pragma unroll
            for (int i = 0; i < 4; ++i) acc[mt][nt][i] = 0.0f;

    for (int kt = 0; kt < 4; ++kt) {
#pragma unroll
        for (int i = 0; i < 4; ++i) {
            int idx = tid + i * 256;
            int r = idx >> 3, q = idx & 7;
            int rg = row0 + r; if (rg > n - 1) rg = n - 1;
            float4 v = *(const float4*)&feat[(size_t)rg * DIN + kt * 32 + q * 4];
            uint2 hp, lp;
            split4(v, hp, lp);
            *(uint2*)&sa_h[r * GAP + q * 4] = hp;
            *(uint2*)&sa_l[r * GAP + q * 4] = lp;
        }
#pragma unroll
        for (int i = 0; i < 2; ++i) {
            int idx = tid + i * 256;
            int r = idx >> 2, q = idx & 3;
            *(uint4*)&sb_h[r * GAP + q * 8] =
                *(const uint4*)&g_wThi[r * 128 + kt * 32 + q * 8];
            *(uint4*)&sb_l[r * GAP + q * 8] =
                *(const uint4*)&g_wTlo[r * 128 + kt * 32 + q * 8];
        }
        __syncthreads();

#pragma unroll
        for (int kc = 0; kc < 2; ++kc) {
            const uint32_t kadd = kc * 32;
            uint32_t bh[8], bl[8];
#pragma unroll
            for (int h = 0; h < 2; ++h) {
                uint32_t boff = (uint32_t)((n0 + h * 16 + (rsel >> 1) * 8 + rin) * GAP
                                           + (rsel & 1) * 8) * 2 + kadd;
                ldmatrix_x4(&bh[h * 4], sbh + boff);
                ldmatrix_x4(&bl[h * 4], sbl + boff);
            }
#pragma unroll
            for (int mt = 0; mt < 4; ++mt) {
                uint32_t aoff = (uint32_t)((m0 + mt * 16 + (rsel & 1) * 8 + rin) * GAP
                                           + (rsel >> 1) * 8) * 2 + kadd;
                uint32_t ah[4], al[4];
                ldmatrix_x4(ah, sah + aoff);
                ldmatrix_x4(al, sal + aoff);
#pragma unroll
                for (int nt = 0; nt < 4; ++nt) {
                    mma_bf16(acc[mt][nt], ah, &bh[nt * 2]);
                    mma_bf16(acc[mt][nt], ah, &bl[nt * 2]);
                    mma_bf16(acc[mt][nt], al, &bh[nt * 2]);
                }
            }
        }
        __syncthreads();
    }

#pragma unroll
    for (int mt = 0; mt < 4; ++mt) {
        int ra = row0 + m0 + mt * 16 + (lane >> 2);
#pragma unroll
        for (int nt = 0; nt < 4; ++nt) {
            int cb = n0 + nt * 8 + 2 * (lane & 3);
            uint32_t hp, lp;
            split2(acc[mt][nt][0], acc[mt][nt][1], hp, lp);
            *(uint32_t*)&g_xhi[(size_t)ra * DOUT + cb] = hp;
            *(uint32_t*)&g_xlo[(size_t)ra * DOUT + cb] = lp;
            split2(acc[mt][nt][2], acc[mt][nt][3], hp, lp);
            *(uint32_t*)&g_xhi[(size_t)(ra + 8) * DOUT + cb] = hp;
            *(uint32_t*)&g_xlo[(size_t)(ra + 8) * DOUT + cb] = lp;
        }
    }
}

// ---------------------------------------------------------------------------
// Kernel B: topk (register rank), symmetric 3-tile Gram, dist, softmax, mma agg
// 1 CTA per node, 128 threads (4 warps)
// ---------------------------------------------------------------------------
#define BPITCH 136

__global__ __launch_bounds__(128) void node_kernel(const float* __restrict__ ew,
                                                   const int*   __restrict__ nbr,
                                                   const float* __restrict__ bias,
                                                   float*       __restrict__ out,
                                                   int n)
{
    __shared__ __align__(16) __nv_bfloat16 xhi[32 * BPITCH];
    __shared__ __align__(16) __nv_bfloat16 xlo[32 * BPITCH];
    __shared__ float selw[32];
    __shared__ int   selid[32];
    __shared__ float ssq[32];
    __shared__ float sdA[32];   // diag-tile dist partials
    __shared__ float sdB[32];   // offdiag-tile dist partials
    __shared__ __align__(4) unsigned short srelh[32];
    __shared__ __align__(4) unsigned short srell[32];
    __shared__ __align__(16) float sout[128];

    const int node = blockIdx.x;
    const int tid  = threadIdx.x;
    const int lane = tid & 31;
    const int wrp  = tid >> 5;

    // --- top-32 of 49: rank via uniform vector loads, no smem staging ---
    if (tid < DEG + 1) {
        float v; int myid;
        if (tid < DEG) {
            v    = ew[(size_t)node * DEG + tid];
            myid = nbr[(size_t)node * DEG + tid];
        } else {
            v = 1.0f; myid = node;
        }
        // j = 48 (self-loop, w=1.0): j < tid never true for tid <= 48
        int rank = (1.0f > v) ? 1 : 0;
        const float4* row = (const float4*)(ew + (size_t)node * DEG);
#pragma unroll
        for (int c = 0; c < 12; ++c) {
            float4 w4 = row[c];
            int j0 = c * 4;
            rank += (w4.x > v) || (w4.x == v && (j0 + 0) < tid);
            rank += (w4.y > v) || (w4.y == v && (j0 + 1) < tid);
            rank += (w4.z > v) || (w4.z == v && (j0 + 2) < tid);
            rank += (w4.w > v) || (w4.w == v && (j0 + 3) < tid);
        }
        if (rank < KSEL) { selw[rank] = v; selid[rank] = myid; }
    }
    __syncthreads();

    // --- gather pre-split bf16 rows (coalesced) ---
    {
        const int r0 = wrp * 8;
        const int c0 = lane * 4;
#pragma unroll
        for (int r = 0; r < 8; ++r) {
            const int row = r0 + r;
            const size_t base = (size_t)selid[row] * DOUT + c0;
            *(uint2*)&xhi[row * BPITCH + c0] = *(const uint2*)&g_xhi[base];
            *(uint2*)&xlo[row * BPITCH + c0] = *(const uint2*)&g_xlo[base];
        }
    }
    __syncthreads();

    // --- Gram, 3 tiles: w0 diag(0,0) A=B aliased, w1 diag(16,16), w2 offdiag ---
    const uint32_t hbase = smem_u32(xhi);
    const uint32_t lbase = smem_u32(xlo);
    const int p = lane >> 2;
    const int q = lane & 3;
    float c0f[4] = {0.f, 0.f, 0.f, 0.f};
    float c1f[4] = {0.f, 0.f, 0.f, 0.f};

    if (wrp < 2) {
        const int m0 = wrp * 16;
        const int rsel = lane >> 3, rin = lane & 7;
        const uint32_t a_off = (uint32_t)((m0 + (rsel & 1) * 8 + rin) * BPITCH
                                          + (rsel >> 1) * 8) * 2;
#pragma unroll
        for (int kc = 0; kc < 8; ++kc) {
            uint32_t ah[4], al[4];
            ldmatrix_x4(ah, hbase + a_off + kc * 32);
            ldmatrix_x4(al, lbase + a_off + kc * 32);
            // B-frags aliased from A-frags (same 8x8 non-trans blocks)
            uint32_t bh0[2] = {ah[0], ah[2]}, bh1[2] = {ah[1], ah[3]};
            uint32_t bl0[2] = {al[0], al[2]}, bl1[2] = {al[1], al[3]};
            mma_bf16(c0f, ah, bh0); mma_bf16(c0f, ah, bl0); mma_bf16(c0f, al, bh0);
            mma_bf16(c1f, ah, bh1); mma_bf16(c1f, ah, bl1); mma_bf16(c1f, al, bh1);
        }
        // diagonal -> ssq
        if (p == 2 * q)     { ssq[m0 + p] = c0f[0]; ssq[m0 + p + 8] = c1f[2]; }
        if (p == 2 * q + 1) { ssq[m0 + p] = c0f[1]; ssq[m0 + p + 8] = c1f[3]; }
    } else if (wrp == 2) {
        const int rsel = lane >> 3, rin = lane & 7;
        const uint32_t a_off = (uint32_t)(((rsel & 1) * 8 + rin) * BPITCH
                                          + (rsel >> 1) * 8) * 2;
        const uint32_t b_off = (uint32_t)((16 + (rsel >> 1) * 8 + rin) * BPITCH
                                          + (rsel & 1) * 8) * 2;
#pragma unroll
        for (int kc = 0; kc < 8; ++kc) {
            uint32_t ah[4], al[4], bh[4], bl[4];
            ldmatrix_x4(ah, hbase + a_off + kc * 32);
            ldmatrix_x4(al, lbase + a_off + kc * 32);
            ldmatrix_x4(bh, hbase + b_off + kc * 32);
            ldmatrix_x4(bl, lbase + b_off + kc * 32);
            mma_bf16(c0f, ah, &bh[0]); mma_bf16(c0f, ah, &bl[0]); mma_bf16(c0f, al, &bh[0]);
            mma_bf16(c1f, ah, &bh[2]); mma_bf16(c1f, ah, &bl[2]); mma_bf16(c1f, al, &bh[2]);
        }
    }
    __syncthreads();   // ssq visible to all

    // --- dist partials ---
    if (wrp < 2) {
        // diag tile: rows/cols m0..m0+15, standard row sums
        const int m0 = wrp * 16;
        const int b0 = m0 + 2 * q, b1 = b0 + 1, b2 = b0 + 8, b3 = b2 + 1;
        const float w0 = selw[b0], w1 = selw[b1], w2 = selw[b2], w3 = selw[b3];
        const float s0 = ssq[b0], s1 = ssq[b1], s2 = ssq[b2], s3 = ssq[b3];
        const float sqa  = ssq[m0 + p];
        const float sqa8 = ssq[m0 + p + 8];

        float d, part = 0.f, part8 = 0.f;
        d = sqa  + s0 - 2.f * c0f[0]; part  = fmaf(w0, (d > 0.f) ? sqrtf(d) : 0.f, part);
        d = sqa  + s1 - 2.f * c0f[1]; part  = fmaf(w1, (d > 0.f) ? sqrtf(d) : 0.f, part);
        d = sqa  + s2 - 2.f * c1f[0]; part  = fmaf(w2, (d > 0.f) ? sqrtf(d) : 0.f, part);
        d = sqa  + s3 - 2.f * c1f[1]; part  = fmaf(w3, (d > 0.f) ? sqrtf(d) : 0.f, part);
        d = sqa8 + s0 - 2.f * c0f[2]; part8 = fmaf(w0, (d > 0.f) ? sqrtf(d) : 0.f, part8);
        d = sqa8 + s1 - 2.f * c0f[3]; part8 = fmaf(w1, (d > 0.f) ? sqrtf(d) : 0.f, part8);
        d = sqa8 + s2 - 2.f * c1f[2]; part8 = fmaf(w2, (d > 0.f) ? sqrtf(d) : 0.f, part8);
        d = sqa8 + s3 - 2.f * c1f[3]; part8 = fmaf(w3, (d > 0.f) ? sqrtf(d) : 0.f, part8);

        part  += __shfl_down_sync(0xffffffffu, part, 2);
        part  += __shfl_down_sync(0xffffffffu, part, 1);
        part8 += __shfl_down_sync(0xffffffffu, part8, 2);
        part8 += __shfl_down_sync(0xffffffffu, part8, 1);
        if (q == 0) { sdA[m0 + p] = part; sdA[m0 + p + 8] = part8; }
    } else if (wrp == 2) {
        // offdiag tile rows 0-15 x cols 16-31: row sums AND w_a-weighted col sums
        const int cA = 16 + 2 * q, cB = cA + 1, cC = cA + 8, cD = cC + 1;
        const float wA = selw[cA], wB = selw[cB], wC = selw[cC], wD = selw[cD];
        const float sA = ssq[cA], sB = ssq[cB], sC = ssq[cC], sD = ssq[cD];
        const float sqa  = ssq[p];
        const float sqa8 = ssq[p + 8];
        const float wp   = selw[p];
        const float wp8  = selw[p + 8];

        float d;
        d = sqa  + sA - 2.f * c0f[0]; float dpA = (d > 0.f) ? sqrtf(d) : 0.f;
        d = sqa  + sB - 2.f * c0f[1]; float dpB = (d > 0.f) ? sqrtf(d) : 0.f;
        d = sqa  + sC - 2.f * c1f[0]; float dpC = (d > 0.f) ? sqrtf(d) : 0.f;
        d = sqa  + sD - 2.f * c1f[1]; float dpD = (d > 0.f) ? sqrtf(d) : 0.f;
        d = sqa8 + sA - 2.f * c0f[2]; float d8A = (d > 0.f) ? sqrtf(d) : 0.f;
        d = sqa8 + sB - 2.f * c0f[3]; float d8B = (d > 0.f) ? sqrtf(d) : 0.f;
        d = sqa8 + sC - 2.f * c1f[2]; float d8C = (d > 0.f) ? sqrtf(d) : 0.f;
        d = sqa8 + sD - 2.f * c1f[3]; float d8D = (d > 0.f) ? sqrtf(d) : 0.f;

        // row part (rows p, p+8 over cols 16-31)
        float part  = wA * dpA + wB * dpB + wC * dpC + wD * dpD;
        float part8 = wA * d8A + wB * d8B + wC * d8C + wD * d8D;
        part  += __shfl_down_sync(0xffffffffu, part, 2);
        part  += __shfl_down_sync(0xffffffffu, part, 1);
        part8 += __shfl_down_sync(0xffffffffu, part8, 2);
        part8 += __shfl_down_sync(0xffffffffu, part8, 1);
        if (q == 0) { sdB[p] = part; sdB[p + 8] = part8; }

        // col part (cols 16-31, weighted by row weights), reduce over p
        float colA = wp * dpA + wp8 * d8A;
        float colB = wp * dpB + wp8 * d8B;
        float colC = wp * dpC + wp8 * d8C;
        float colD = wp * dpD + wp8 * d8D;
#pragma unroll
        for (int off = 4; off <= 16; off <<= 1) {
            colA += __shfl_xor_sync(0xffffffffu, colA, off);
            colB += __shfl_xor_sync(0xffffffffu, colB, off);
            colC += __shfl_xor_sync(0xffffffffu, colC, off);
            colD += __shfl_xor_sync(0xffffffffu, colD, off);
        }
        if (lane < 4) {
            *(float2*)&sdB[16 + 2 * lane] = make_float2(colA, colB);
            *(float2*)&sdB[24 + 2 * lane] = make_float2(colC, colD);
        }
    }
    __syncthreads();

    // --- softmax(-dist) * tw, renormalized; emit rel hi/lo ---
    if (tid < 32) {
        float v = sdA[tid] + sdB[tid];
        float m = v;
#pragma unroll
        for (int off = 16; off; off >>= 1)
            m = fminf(m, __shfl_xor_sync(0xffffffffu, m, off));
        float r = expf(m - v) * selw[tid];
        float s = r;
#pragma unroll
        for (int off = 16; off; off >>= 1)
            s += __shfl_xor_sync(0xffffffffu, s, off);
        float rr = r / s;
        uint32_t bits = __float_as_uint(rr);
        srelh[tid] = (unsigned short)(bits >> 16);
        float rl = rr - __uint_as_float(bits & 0xffff0000u);
        srell[tid] = __bfloat16_as_ushort(__float2bfloat16_rn(rl));
    }
    __syncthreads();

    // --- aggregation via mma: out = rel^T @ X; warp w covers cols 32w..32w+31 ---
    {
        const uint32_t* relh32 = (const uint32_t*)srelh;
        const uint32_t* rell32 = (const uint32_t*)srell;
        const int n0w = wrp * 32;
        const int g = lane >> 3, rr = lane & 7;

        float cagg[4][4];
#pragma unroll
        for (int i = 0; i < 4; ++i)
#pragma unroll
            for (int j = 0; j < 4; ++j) cagg[i][j] = 0.f;

#pragma unroll
        for (int kc = 0; kc < 2; ++kc) {
            uint32_t ah[4], al[4];
            ah[0] = relh32[kc * 8 + q];     ah[1] = ah[0];
            ah[2] = relh32[kc * 8 + 4 + q]; ah[3] = ah[2];
            al[0] = rell32[kc * 8 + q];     al[1] = al[0];
            al[2] = rell32[kc * 8 + 4 + q]; al[3] = al[2];

#pragma unroll
            for (int t = 0; t < 2; ++t) {
                const int nA = n0w + t * 16;
                uint32_t addr_off = (uint32_t)(((kc * 16 + (g & 1) * 8 + rr) * BPITCH
                                               + nA + (g >> 1) * 8) * 2);
                uint32_t bh[4], bl[4];
                ldmatrix_x4_trans(bh, hbase + addr_off);
                ldmatrix_x4_trans(bl, lbase + addr_off);

                mma_bf16(cagg[2 * t], ah, &bh[0]);
                mma_bf16(cagg[2 * t], ah, &bl[0]);
                mma_bf16(cagg[2 * t], al, &bh[0]);
                mma_bf16(cagg[2 * t + 1], ah, &bh[2]);
                mma_bf16(cagg[2 * t + 1], ah, &bl[2]);
                mma_bf16(cagg[2 * t + 1], al, &bh[2]);
            }
        }

        if (lane < 4) {
#pragma unroll
            for (int i = 0; i < 4; ++i)
                *(float2*)&sout[n0w + i * 8 + 2 * lane] =
                    make_float2(cagg[i][0], cagg[i][1]);
        }
    }
    __syncthreads();

    out[(size_t)node * DOUT + tid] = sout[tid] + bias[tid];
}

// ---------------------------------------------------------------------------
// Launch
// ---------------------------------------------------------------------------
extern "C" void kernel_launch(void* const* d_in, const int* in_sizes, int n_in,
                              void* d_out, int out_size)
{
    const float* feat   = (const float*)d_in[0];
    const float* ew     = (const float*)d_in[1];
    const float* weight = (const float*)d_in[2];
    const float* bias   = (const float*)d_in[3];
    const int*   nbr    = (const int*)  d_in[4];
    float*       out    = (float*)d_out;

    int n = in_sizes[0] / DIN;

    wsplit_kernel<<<64, 256>>>(weight);
    gemm_kernel<<<(n + 127) / 128, 256>>>(feat, n);
    node_kernel<<<n, 128>>>(ew, nbr, bias, out, n);
}

// round 11
// speedup vs baseline: 1.6441x; 1.1083x over previous
#include <cuda_runtime.h>
#include <cuda_bf16.h>
#include <cstdint>

// Problem constants
#define DIN   128
#define DOUT  128
#define DEG   48
#define KSEL  32
#define NPAD  50048

// Interleaved split storage: per node 256 bf16 = [128 hi][128 lo] (512 B row)
__device__ __nv_bfloat16 g_xs[(size_t)NPAD * 256];
__device__ __nv_bfloat16 g_wThi[128 * 128];            // W^T hi, [n][k]
__device__ __nv_bfloat16 g_wTlo[128 * 128];            // W^T lo, [n][k]

// ---------------------------------------------------------------------------
// Common helpers
// ---------------------------------------------------------------------------
__device__ __forceinline__ uint32_t smem_u32(const void* p) {
    uint32_t a;
    asm("{ .reg .u64 t; cvta.to.shared.u64 t, %1; cvt.u32.u64 %0, t; }" : "=r"(a) : "l"(p));
    return a;
}

__device__ __forceinline__ void ldmatrix_x4(uint32_t* r, uint32_t addr) {
    asm volatile("ldmatrix.sync.aligned.m8n8.x4.shared.b16 {%0,%1,%2,%3}, [%4];"
                 : "=r"(r[0]), "=r"(r[1]), "=r"(r[2]), "=r"(r[3]) : "r"(addr));
}

__device__ __forceinline__ void ldmatrix_x4_trans(uint32_t* r, uint32_t addr) {
    asm volatile("ldmatrix.sync.aligned.m8n8.x4.trans.shared.b16 {%0,%1,%2,%3}, [%4];"
                 : "=r"(r[0]), "=r"(r[1]), "=r"(r[2]), "=r"(r[3]) : "r"(addr));
}

__device__ __forceinline__ void mma_bf16(float* c, const uint32_t* a, const uint32_t* b) {
    asm volatile(
        "mma.sync.aligned.m16n8k16.row.col.f32.bf16.bf16.f32 "
        "{%0,%1,%2,%3}, {%4,%5,%6,%7}, {%8,%9}, {%0,%1,%2,%3};"
        : "+f"(c[0]), "+f"(c[1]), "+f"(c[2]), "+f"(c[3])
        : "r"(a[0]), "r"(a[1]), "r"(a[2]), "r"(a[3]), "r"(b[0]), "r"(b[1]));
}

// Truncation split: hi = top-16 bits of fp32, lo = rn-bf16 of (x - hi).
__device__ __forceinline__ void split4(float4 v, uint2& hp, uint2& lp) {
    uint32_t ax = __float_as_uint(v.x), ay = __float_as_uint(v.y);
    uint32_t az = __float_as_uint(v.z), aw = __float_as_uint(v.w);
    hp.x = __byte_perm(ax, ay, 0x7632);
    hp.y = __byte_perm(az, aw, 0x7632);
    float lx = v.x - __uint_as_float(ax & 0xffff0000u);
    float ly = v.y - __uint_as_float(ay & 0xffff0000u);
    float lz = v.z - __uint_as_float(az & 0xffff0000u);
    float lw = v.w - __uint_as_float(aw & 0xffff0000u);
    asm("cvt.rn.bf16x2.f32 %0, %1, %2;" : "=r"(lp.x) : "f"(ly), "f"(lx));
    asm("cvt.rn.bf16x2.f32 %0, %1, %2;" : "=r"(lp.y) : "f"(lw), "f"(lz));
}

__device__ __forceinline__ void split2(float x, float y, uint32_t& hp, uint32_t& lp) {
    uint32_t ax = __float_as_uint(x), ay = __float_as_uint(y);
    hp = __byte_perm(ax, ay, 0x7632);
    float lx = x - __uint_as_float(ax & 0xffff0000u);
    float ly = y - __uint_as_float(ay & 0xffff0000u);
    asm("cvt.rn.bf16x2.f32 %0, %1, %2;" : "=r"(lp) : "f"(ly), "f"(lx));
}

// ---------------------------------------------------------------------------
// Kernel 0: transpose + split W -> g_wThi/g_wTlo  ([n][k] bf16)
// ---------------------------------------------------------------------------
__global__ __launch_bounds__(256) void wsplit_kernel(const float* __restrict__ W)
{
    int idx = blockIdx.x * 256 + threadIdx.x;
    int k = idx >> 7, nn = idx & 127;
    float v = W[k * 128 + nn];
    uint32_t b = __float_as_uint(v);
    uint32_t hbits = b & 0xffff0000u;
    float lo = v - __uint_as_float(hbits);
    g_wThi[nn * 128 + k] = __ushort_as_bfloat16((unsigned short)(hbits >> 16));
    g_wTlo[nn * 128 + k] = __float2bfloat16_rn(lo);
}

// ---------------------------------------------------------------------------
// Kernel A: x = feat @ W via bf16 3-pass mma.sync; epilogue -> interleaved g_xs
// ---------------------------------------------------------------------------
#define GAP 40   // bf16 smem pitch (80 B), ldmatrix conflict-free

__global__ __launch_bounds__(256) void gemm_kernel(const float* __restrict__ feat,
                                                   int n)
{
    __shared__ __align__(16) __nv_bfloat16 sa_h[128 * GAP];
    __shared__ __align__(16) __nv_bfloat16 sa_l[128 * GAP];
    __shared__ __align__(16) __nv_bfloat16 sb_h[128 * GAP];
    __shared__ __align__(16) __nv_bfloat16 sb_l[128 * GAP];

    const int tid  = threadIdx.x;
    const int lane = tid & 31;
    const int wrp  = tid >> 5;
    const int row0 = blockIdx.x * 128;

    const int m0 = (wrp & 1) * 64;
    const int n0 = (wrp >> 1) * 32;
    const int rsel = lane >> 3, rin = lane & 7;

    const uint32_t sah = smem_u32(sa_h), sal = smem_u32(sa_l);
    const uint32_t sbh = smem_u32(sb_h), sbl = smem_u32(sb_l);

    float acc[4][4][4];
#pragma unroll
    for (int mt = 0; mt < 4; ++mt)
#pragma unroll
        for (int nt = 0; nt < 4; ++nt)
#pragma unroll
            for (int i = 0; i < 4; ++i) acc[mt][nt][i] = 0.0f;

    for (int kt = 0; kt < 4; ++kt) {
#pragma unroll
        for (int i = 0; i < 4; ++i) {
            int idx = tid + i * 256;
            int r = idx >> 3, q = idx & 7;
            int rg = row0 + r; if (rg > n - 1) rg = n - 1;
            float4 v = *(const float4*)&feat[(size_t)rg * DIN + kt * 32 + q * 4];
            uint2 hp, lp;
            split4(v, hp, lp);
            *(uint2*)&sa_h[r * GAP + q * 4] = hp;
            *(uint2*)&sa_l[r * GAP + q * 4] = lp;
        }
#pragma unroll
        for (int i = 0; i < 2; ++i) {
            int idx = tid + i * 256;
            int r = idx >> 2, q = idx & 3;
            *(uint4*)&sb_h[r * GAP + q * 8] =
                *(const uint4*)&g_wThi[r * 128 + kt * 32 + q * 8];
            *(uint4*)&sb_l[r * GAP + q * 8] =
                *(const uint4*)&g_wTlo[r * 128 + kt * 32 + q * 8];
        }
        __syncthreads();

#pragma unroll
        for (int kc = 0; kc < 2; ++kc) {
            const uint32_t kadd = kc * 32;
            uint32_t bh[8], bl[8];
#pragma unroll
            for (int h = 0; h < 2; ++h) {
                uint32_t boff = (uint32_t)((n0 + h * 16 + (rsel >> 1) * 8 + rin) * GAP
                                           + (rsel & 1) * 8) * 2 + kadd;
                ldmatrix_x4(&bh[h * 4], sbh + boff);
                ldmatrix_x4(&bl[h * 4], sbl + boff);
            }
#pragma unroll
            for (int mt = 0; mt < 4; ++mt) {
                uint32_t aoff = (uint32_t)((m0 + mt * 16 + (rsel & 1) * 8 + rin) * GAP
                                           + (rsel >> 1) * 8) * 2 + kadd;
                uint32_t ah[4], al[4];
                ldmatrix_x4(ah, sah + aoff);
                ldmatrix_x4(al, sal + aoff);
#pragma unroll
                for (int nt = 0; nt < 4; ++nt) {
                    mma_bf16(acc[mt][nt], ah, &bh[nt * 2]);
                    mma_bf16(acc[mt][nt], ah, &bl[nt * 2]);
                    mma_bf16(acc[mt][nt], al, &bh[nt * 2]);
                }
            }
        }
        __syncthreads();
    }

    // epilogue: trunc-split, store interleaved [128 hi][128 lo] per node row
#pragma unroll
    for (int mt = 0; mt < 4; ++mt) {
        int ra = row0 + m0 + mt * 16 + (lane >> 2);
#pragma unroll
        for (int nt = 0; nt < 4; ++nt) {
            int cb = n0 + nt * 8 + 2 * (lane & 3);
            uint32_t hp, lp;
            split2(acc[mt][nt][0], acc[mt][nt][1], hp, lp);
            *(uint32_t*)&g_xs[(size_t)ra * 256 + cb]       = hp;
            *(uint32_t*)&g_xs[(size_t)ra * 256 + 128 + cb] = lp;
            split2(acc[mt][nt][2], acc[mt][nt][3], hp, lp);
            *(uint32_t*)&g_xs[(size_t)(ra + 8) * 256 + cb]       = hp;
            *(uint32_t*)&g_xs[(size_t)(ra + 8) * 256 + 128 + cb] = lp;
        }
    }
}

// ---------------------------------------------------------------------------
// Kernel B: topk (register rank), cp.async gather, symmetric 3-tile Gram,
//           in-fragment dist, softmax, mma agg.   1 CTA/node, 128 threads.
// ---------------------------------------------------------------------------
#define BPITCH 136

__global__ __launch_bounds__(128) void node_kernel(const float* __restrict__ ew,
                                                   const int*   __restrict__ nbr,
                                                   const float* __restrict__ bias,
                                                   float*       __restrict__ out,
                                                   int n)
{
    __shared__ __align__(16) __nv_bfloat16 xhi[32 * BPITCH];
    __shared__ __align__(16) __nv_bfloat16 xlo[32 * BPITCH];
    __shared__ float selw[32];
    __shared__ int   selid[32];
    __shared__ float ssq[32];
    __shared__ float sdA[32];
    __shared__ float sdB[32];
    __shared__ __align__(4) unsigned short srelh[32];
    __shared__ __align__(4) unsigned short srell[32];
    __shared__ __align__(16) float sout[128];

    const int node = blockIdx.x;
    const int tid  = threadIdx.x;
    const int lane = tid & 31;
    const int wrp  = tid >> 5;

    // --- top-32 of 49: rank via uniform vector loads, no smem staging ---
    if (tid < DEG + 1) {
        float v; int myid;
        if (tid < DEG) {
            v    = ew[(size_t)node * DEG + tid];
            myid = nbr[(size_t)node * DEG + tid];
        } else {
            v = 1.0f; myid = node;
        }
        int rank = (1.0f > v) ? 1 : 0;   // self-loop j=48: j<tid never for tid<=48
        const float4* row = (const float4*)(ew + (size_t)node * DEG);
#pragma unroll
        for (int c = 0; c < 12; ++c) {
            float4 w4 = row[c];
            int j0 = c * 4;
            rank += (w4.x > v) || (w4.x == v && (j0 + 0) < tid);
            rank += (w4.y > v) || (w4.y == v && (j0 + 1) < tid);
            rank += (w4.z > v) || (w4.z == v && (j0 + 2) < tid);
            rank += (w4.w > v) || (w4.w == v && (j0 + 3) < tid);
        }
        if (rank < KSEL) { selw[rank] = v; selid[rank] = myid; }
    }
    __syncthreads();

    // --- gather via cp.async: 1 row = 512B = 32 lanes x 16B ---
    // lanes 0-15 -> xhi row bytes, lanes 16-31 -> xlo row bytes
    {
        const int r0 = wrp * 8;
        const uint32_t hbase0 = smem_u32(xhi);
        const uint32_t lbase0 = smem_u32(xlo);
        const uint32_t dbase  = (lane < 16 ? hbase0 : lbase0) + (lane & 15) * 16;
#pragma unroll
        for (int r = 0; r < 8; ++r) {
            const int row = r0 + r;
            const char* src = (const char*)g_xs + (size_t)selid[row] * 512 + lane * 16;
            uint32_t dst = dbase + (uint32_t)(row * (BPITCH * 2));
            asm volatile("cp.async.ca.shared.global [%0], [%1], 16;"
                         :: "r"(dst), "l"(src));
        }
        asm volatile("cp.async.commit_group;");
        asm volatile("cp.async.wait_group 0;");
    }
    __syncthreads();

    // --- Gram, 3 tiles: w0 diag(0,0) A=B aliased, w1 diag(16,16), w2 offdiag ---
    const uint32_t hbase = smem_u32(xhi);
    const uint32_t lbase = smem_u32(xlo);
    const int p = lane >> 2;
    const int q = lane & 3;
    float c0f[4] = {0.f, 0.f, 0.f, 0.f};
    float c1f[4] = {0.f, 0.f, 0.f, 0.f};

    if (wrp < 2) {
        const int m0 = wrp * 16;
        const int rsel = lane >> 3, rin = lane & 7;
        const uint32_t a_off = (uint32_t)((m0 + (rsel & 1) * 8 + rin) * BPITCH
                                          + (rsel >> 1) * 8) * 2;
#pragma unroll
        for (int kc = 0; kc < 8; ++kc) {
            uint32_t ah[4], al[4];
            ldmatrix_x4(ah, hbase + a_off + kc * 32);
            ldmatrix_x4(al, lbase + a_off + kc * 32);
            uint32_t bh0[2] = {ah[0], ah[2]}, bh1[2] = {ah[1], ah[3]};
            uint32_t bl0[2] = {al[0], al[2]}, bl1[2] = {al[1], al[3]};
            mma_bf16(c0f, ah, bh0); mma_bf16(c0f, ah, bl0); mma_bf16(c0f, al, bh0);
            mma_bf16(c1f, ah, bh1); mma_bf16(c1f, ah, bl1); mma_bf16(c1f, al, bh1);
        }
        if (p == 2 * q)     { ssq[m0 + p] = c0f[0]; ssq[m0 + p + 8] = c1f[2]; }
        if (p == 2 * q + 1) { ssq[m0 + p] = c0f[1]; ssq[m0 + p + 8] = c1f[3]; }
    } else if (wrp == 2) {
        const int rsel = lane >> 3, rin = lane & 7;
        const uint32_t a_off = (uint32_t)(((rsel & 1) * 8 + rin) * BPITCH
                                          + (rsel >> 1) * 8) * 2;
        const uint32_t b_off = (uint32_t)((16 + (rsel >> 1) * 8 + rin) * BPITCH
                                          + (rsel & 1) * 8) * 2;
#pragma unroll
        for (int kc = 0; kc < 8; ++kc) {
            uint32_t ah[4], al[4], bh[4], bl[4];
            ldmatrix_x4(ah, hbase + a_off + kc * 32);
            ldmatrix_x4(al, lbase + a_off + kc * 32);
            ldmatrix_x4(bh, hbase + b_off + kc * 32);
            ldmatrix_x4(bl, lbase + b_off + kc * 32);
            mma_bf16(c0f, ah, &bh[0]); mma_bf16(c0f, ah, &bl[0]); mma_bf16(c0f, al, &bh[0]);
            mma_bf16(c1f, ah, &bh[2]); mma_bf16(c1f, ah, &bl[2]); mma_bf16(c1f, al, &bh[2]);
        }
    }
    __syncthreads();

    // --- dist partials ---
    if (wrp < 2) {
        const int m0 = wrp * 16;
        const int b0 = m0 + 2 * q, b1 = b0 + 1, b2 = b0 + 8, b3 = b2 + 1;
        const float w0 = selw[b0], w1 = selw[b1], w2 = selw[b2], w3 = selw[b3];
        const float s0 = ssq[b0], s1 = ssq[b1], s2 = ssq[b2], s3 = ssq[b3];
        const float sqa  = ssq[m0 + p];
        const float sqa8 = ssq[m0 + p + 8];

        float d, part = 0.f, part8 = 0.f;
        d = sqa  + s0 - 2.f * c0f[0]; part  = fmaf(w0, (d > 0.f) ? sqrtf(d) : 0.f, part);
        d = sqa  + s1 - 2.f * c0f[1]; part  = fmaf(w1, (d > 0.f) ? sqrtf(d) : 0.f, part);
        d = sqa  + s2 - 2.f * c1f[0]; part  = fmaf(w2, (d > 0.f) ? sqrtf(d) : 0.f, part);
        d = sqa  + s3 - 2.f * c1f[1]; part  = fmaf(w3, (d > 0.f) ? sqrtf(d) : 0.f, part);
        d = sqa8 + s0 - 2.f * c0f[2]; part8 = fmaf(w0, (d > 0.f) ? sqrtf(d) : 0.f, part8);
        d = sqa8 + s1 - 2.f * c0f[3]; part8 = fmaf(w1, (d > 0.f) ? sqrtf(d) : 0.f, part8);
        d = sqa8 + s2 - 2.f * c1f[2]; part8 = fmaf(w2, (d > 0.f) ? sqrtf(d) : 0.f, part8);
        d = sqa8 + s3 - 2.f * c1f[3]; part8 = fmaf(w3, (d > 0.f) ? sqrtf(d) : 0.f, part8);

        part  += __shfl_down_sync(0xffffffffu, part, 2);
        part  += __shfl_down_sync(0xffffffffu, part, 1);
        part8 += __shfl_down_sync(0xffffffffu, part8, 2);
        part8 += __shfl_down_sync(0xffffffffu, part8, 1);
        if (q == 0) { sdA[m0 + p] = part; sdA[m0 + p + 8] = part8; }
    } else if (wrp == 2) {
        const int cA = 16 + 2 * q, cB = cA + 1, cC = cA + 8, cD = cC + 1;
        const float wA = selw[cA], wB = selw[cB], wC = selw[cC], wD = selw[cD];
        const float sA = ssq[cA], sB = ssq[cB], sC = ssq[cC], sD = ssq[cD];
        const float sqa  = ssq[p];
        const float sqa8 = ssq[p + 8];
        const float wp   = selw[p];
        const float wp8  = selw[p + 8];

        float d;
        d = sqa  + sA - 2.f * c0f[0]; float dpA = (d > 0.f) ? sqrtf(d) : 0.f;
        d = sqa  + sB - 2.f * c0f[1]; float dpB = (d > 0.f) ? sqrtf(d) : 0.f;
        d = sqa  + sC - 2.f * c1f[0]; float dpC = (d > 0.f) ? sqrtf(d) : 0.f;
        d = sqa  + sD - 2.f * c1f[1]; float dpD = (d > 0.f) ? sqrtf(d) : 0.f;
        d = sqa8 + sA - 2.f * c0f[2]; float d8A = (d > 0.f) ? sqrtf(d) : 0.f;
        d = sqa8 + sB - 2.f * c0f[3]; float d8B = (d > 0.f) ? sqrtf(d) : 0.f;
        d = sqa8 + sC - 2.f * c1f[2]; float d8C = (d > 0.f) ? sqrtf(d) : 0.f;
        d = sqa8 + sD - 2.f * c1f[3]; float d8D = (d > 0.f) ? sqrtf(d) : 0.f;

        float part  = wA * dpA + wB * dpB + wC * dpC + wD * dpD;
        float part8 = wA * d8A + wB * d8B + wC * d8C + wD * d8D;
        part  += __shfl_down_sync(0xffffffffu, part, 2);
        part  += __shfl_down_sync(0xffffffffu, part, 1);
        part8 += __shfl_down_sync(0xffffffffu, part8, 2);
        part8 += __shfl_down_sync(0xffffffffu, part8, 1);
        if (q == 0) { sdB[p] = part; sdB[p + 8] = part8; }

        float colA = wp * dpA + wp8 * d8A;
        float colB = wp * dpB + wp8 * d8B;
        float colC = wp * dpC + wp8 * d8C;
        float colD = wp * dpD + wp8 * d8D;
#pragma unroll
        for (int off = 4; off <= 16; off <<= 1) {
            colA += __shfl_xor_sync(0xffffffffu, colA, off);
            colB += __shfl_xor_sync(0xffffffffu, colB, off);
            colC += __shfl_xor_sync(0xffffffffu, colC, off);
            colD += __shfl_xor_sync(0xffffffffu, colD, off);
        }
        if (lane < 4) {
            *(float2*)&sdB[16 + 2 * lane] = make_float2(colA, colB);
            *(float2*)&sdB[24 + 2 * lane] = make_float2(colC, colD);
        }
    }
    __syncthreads();

    // --- softmax(-dist) * tw, renormalized; emit rel hi/lo ---
    if (tid < 32) {
        float v = sdA[tid] + sdB[tid];
        float m = v;
#pragma unroll
        for (int off = 16; off; off >>= 1)
            m = fminf(m, __shfl_xor_sync(0xffffffffu, m, off));
        float r = expf(m - v) * selw[tid];
        float s = r;
#pragma unroll
        for (int off = 16; off; off >>= 1)
            s += __shfl_xor_sync(0xffffffffu, s, off);
        float rr = r / s;
        uint32_t bits = __float_as_uint(rr);
        srelh[tid] = (unsigned short)(bits >> 16);
        float rl = rr - __uint_as_float(bits & 0xffff0000u);
        srell[tid] = __bfloat16_as_ushort(__float2bfloat16_rn(rl));
    }
    __syncthreads();

    // --- aggregation via mma: out = rel^T @ X; warp w covers cols 32w..32w+31 ---
    {
        const uint32_t* relh32 = (const uint32_t*)srelh;
        const uint32_t* rell32 = (const uint32_t*)srell;
        const int n0w = wrp * 32;
        const int g = lane >> 3, rr = lane & 7;

        float cagg[4][4];
#pragma unroll
        for (int i = 0; i < 4; ++i)
#pragma unroll
            for (int j = 0; j < 4; ++j) cagg[i][j] = 0.f;

#pragma unroll
        for (int kc = 0; kc < 2; ++kc) {
            uint32_t ah[4], al[4];
            ah[0] = relh32[kc * 8 + q];     ah[1] = ah[0];
            ah[2] = relh32[kc * 8 + 4 + q]; ah[3] = ah[2];
            al[0] = rell32[kc * 8 + q];     al[1] = al[0];
            al[2] = rell32[kc * 8 + 4 + q]; al[3] = al[2];

#pragma unroll
            for (int t = 0; t < 2; ++t) {
                const int nA = n0w + t * 16;
                uint32_t addr_off = (uint32_t)(((kc * 16 + (g & 1) * 8 + rr) * BPITCH
                                               + nA + (g >> 1) * 8) * 2);
                uint32_t bh[4], bl[4];
                ldmatrix_x4_trans(bh, hbase + addr_off);
                ldmatrix_x4_trans(bl, lbase + addr_off);

                mma_bf16(cagg[2 * t], ah, &bh[0]);
                mma_bf16(cagg[2 * t], ah, &bl[0]);
                mma_bf16(cagg[2 * t], al, &bh[0]);
                mma_bf16(cagg[2 * t + 1], ah, &bh[2]);
                mma_bf16(cagg[2 * t + 1], ah, &bl[2]);
                mma_bf16(cagg[2 * t + 1], al, &bh[2]);
            }
        }

        if (lane < 4) {
#pragma unroll
            for (int i = 0; i < 4; ++i)
                *(float2*)&sout[n0w + i * 8 + 2 * lane] =
                    make_float2(cagg[i][0], cagg[i][1]);
        }
    }
    __syncthreads();

    out[(size_t)node * DOUT + tid] = sout[tid] + bias[tid];
}

// ---------------------------------------------------------------------------
// Launch
// ---------------------------------------------------------------------------
extern "C" void kernel_launch(void* const* d_in, const int* in_sizes, int n_in,
                              void* d_out, int out_size)
{
    const float* feat   = (const float*)d_in[0];
    const float* ew     = (const float*)d_in[1];
    const float* weight = (const float*)d_in[2];
    const float* bias   = (const float*)d_in[3];
    const int*   nbr    = (const int*)  d_in[4];
    float*       out    = (float*)d_out;

    int n = in_sizes[0] / DIN;

    wsplit_kernel<<<64, 256>>>(weight);
    gemm_kernel<<<(n + 127) / 128, 256>>>(feat, n);
    node_kernel<<<n, 128>>>(ew, nbr, bias, out, n);
}

// round 12
// speedup vs baseline: 1.6998x; 1.0338x over previous
#include <cuda_runtime.h>
#include <cuda_bf16.h>
#include <cstdint>

// Problem constants
#define DIN   128
#define DOUT  128
#define DEG   48
#define KSEL  32
#define NPAD  50048

// Interleaved split storage: per node 256 bf16 = [128 hi][128 lo] (512 B row)
__device__ __nv_bfloat16 g_xs[(size_t)NPAD * 256];
__device__ __nv_bfloat16 g_wThi[128 * 128];            // W^T hi, [n][k]
__device__ __nv_bfloat16 g_wTlo[128 * 128];            // W^T lo, [n][k]

// ---------------------------------------------------------------------------
// Common helpers
// ---------------------------------------------------------------------------
__device__ __forceinline__ uint32_t smem_u32(const void* p) {
    uint32_t a;
    asm("{ .reg .u64 t; cvta.to.shared.u64 t, %1; cvt.u32.u64 %0, t; }" : "=r"(a) : "l"(p));
    return a;
}

__device__ __forceinline__ void ldmatrix_x4(uint32_t* r, uint32_t addr) {
    asm volatile("ldmatrix.sync.aligned.m8n8.x4.shared.b16 {%0,%1,%2,%3}, [%4];"
                 : "=r"(r[0]), "=r"(r[1]), "=r"(r[2]), "=r"(r[3]) : "r"(addr));
}

__device__ __forceinline__ void ldmatrix_x4_trans(uint32_t* r, uint32_t addr) {
    asm volatile("ldmatrix.sync.aligned.m8n8.x4.trans.shared.b16 {%0,%1,%2,%3}, [%4];"
                 : "=r"(r[0]), "=r"(r[1]), "=r"(r[2]), "=r"(r[3]) : "r"(addr));
}

__device__ __forceinline__ void mma_bf16(float* c, const uint32_t* a, const uint32_t* b) {
    asm volatile(
        "mma.sync.aligned.m16n8k16.row.col.f32.bf16.bf16.f32 "
        "{%0,%1,%2,%3}, {%4,%5,%6,%7}, {%8,%9}, {%0,%1,%2,%3};"
        : "+f"(c[0]), "+f"(c[1]), "+f"(c[2]), "+f"(c[3])
        : "r"(a[0]), "r"(a[1]), "r"(a[2]), "r"(a[3]), "r"(b[0]), "r"(b[1]));
}

__device__ __forceinline__ float sqrt_approx(float x) {
    float y;
    asm("sqrt.approx.f32 %0, %1;" : "=f"(y) : "f"(x));
    return y;
}

// Truncation split: hi = top-16 bits of fp32, lo = rn-bf16 of (x - hi).
__device__ __forceinline__ void split4(float4 v, uint2& hp, uint2& lp) {
    uint32_t ax = __float_as_uint(v.x), ay = __float_as_uint(v.y);
    uint32_t az = __float_as_uint(v.z), aw = __float_as_uint(v.w);
    hp.x = __byte_perm(ax, ay, 0x7632);
    hp.y = __byte_perm(az, aw, 0x7632);
    float lx = v.x - __uint_as_float(ax & 0xffff0000u);
    float ly = v.y - __uint_as_float(ay & 0xffff0000u);
    float lz = v.z - __uint_as_float(az & 0xffff0000u);
    float lw = v.w - __uint_as_float(aw & 0xffff0000u);
    asm("cvt.rn.bf16x2.f32 %0, %1, %2;" : "=r"(lp.x) : "f"(ly), "f"(lx));
    asm("cvt.rn.bf16x2.f32 %0, %1, %2;" : "=r"(lp.y) : "f"(lw), "f"(lz));
}

__device__ __forceinline__ void split2(float x, float y, uint32_t& hp, uint32_t& lp) {
    uint32_t ax = __float_as_uint(x), ay = __float_as_uint(y);
    hp = __byte_perm(ax, ay, 0x7632);
    float lx = x - __uint_as_float(ax & 0xffff0000u);
    float ly = y - __uint_as_float(ay & 0xffff0000u);
    asm("cvt.rn.bf16x2.f32 %0, %1, %2;" : "=r"(lp) : "f"(ly), "f"(lx));
}

// ---------------------------------------------------------------------------
// Kernel 0: transpose + split W -> g_wThi/g_wTlo  ([n][k] bf16)
// ---------------------------------------------------------------------------
__global__ __launch_bounds__(256) void wsplit_kernel(const float* __restrict__ W)
{
    int idx = blockIdx.x * 256 + threadIdx.x;
    int k = idx >> 7, nn = idx & 127;
    float v = W[k * 128 + nn];
    uint32_t b = __float_as_uint(v);
    uint32_t hbits = b & 0xffff0000u;
    float lo = v - __uint_as_float(hbits);
    g_wThi[nn * 128 + k] = __ushort_as_bfloat16((unsigned short)(hbits >> 16));
    g_wTlo[nn * 128 + k] = __float2bfloat16_rn(lo);
}

// ---------------------------------------------------------------------------
// Kernel A: x = feat @ W via bf16 3-pass mma.sync; epilogue -> interleaved g_xs
// ---------------------------------------------------------------------------
#define GAP 40   // bf16 smem pitch (80 B), ldmatrix conflict-free

__global__ __launch_bounds__(256) void gemm_kernel(const float* __restrict__ feat,
                                                   int n)
{
    __shared__ __align__(16) __nv_bfloat16 sa_h[128 * GAP];
    __shared__ __align__(16) __nv_bfloat16 sa_l[128 * GAP];
    __shared__ __align__(16) __nv_bfloat16 sb_h[128 * GAP];
    __shared__ __align__(16) __nv_bfloat16 sb_l[128 * GAP];

    const int tid  = threadIdx.x;
    const int lane = tid & 31;
    const int wrp  = tid >> 5;
    const int row0 = blockIdx.x * 128;

    const int m0 = (wrp & 1) * 64;
    const int n0 = (wrp >> 1) * 32;
    const int rsel = lane >> 3, rin = lane & 7;

    const uint32_t sah = smem_u32(sa_h), sal = smem_u32(sa_l);
    const uint32_t sbh = smem_u32(sb_h), sbl = smem_u32(sb_l);

    float acc[4][4][4];
#pragma unroll
    for (int mt = 0; mt < 4; ++mt)
#pragma unroll
        for (int nt = 0; nt < 4; ++nt)
#pragma unroll
            for (int i = 0; i < 4; ++i) acc[mt][nt][i] = 0.0f;

    for (int kt = 0; kt < 4; ++kt) {
#pragma unroll
        for (int i = 0; i < 4; ++i) {
            int idx = tid + i * 256;
            int r = idx >> 3, q = idx & 7;
            int rg = row0 + r; if (rg > n - 1) rg = n - 1;
            float4 v = *(const float4*)&feat[(size_t)rg * DIN + kt * 32 + q * 4];
            uint2 hp, lp;
            split4(v, hp, lp);
            *(uint2*)&sa_h[r * GAP + q * 4] = hp;
            *(uint2*)&sa_l[r * GAP + q * 4] = lp;
        }
#pragma unroll
        for (int i = 0; i < 2; ++i) {
            int idx = tid + i * 256;
            int r = idx >> 2, q = idx & 3;
            *(uint4*)&sb_h[r * GAP + q * 8] =
                *(const uint4*)&g_wThi[r * 128 + kt * 32 + q * 8];
            *(uint4*)&sb_l[r * GAP + q * 8] =
                *(const uint4*)&g_wTlo[r * 128 + kt * 32 + q * 8];
        }
        __syncthreads();

#pragma unroll
        for (int kc = 0; kc < 2; ++kc) {
            const uint32_t kadd = kc * 32;
            uint32_t bh[8], bl[8];
#pragma unroll
            for (int h = 0; h < 2; ++h) {
                uint32_t boff = (uint32_t)((n0 + h * 16 + (rsel >> 1) * 8 + rin) * GAP
                                           + (rsel & 1) * 8) * 2 + kadd;
                ldmatrix_x4(&bh[h * 4], sbh + boff);
                ldmatrix_x4(&bl[h * 4], sbl + boff);
            }
#pragma unroll
            for (int mt = 0; mt < 4; ++mt) {
                uint32_t aoff = (uint32_t)((m0 + mt * 16 + (rsel & 1) * 8 + rin) * GAP
                                           + (rsel >> 1) * 8) * 2 + kadd;
                uint32_t ah[4], al[4];
                ldmatrix_x4(ah, sah + aoff);
                ldmatrix_x4(al, sal + aoff);
#pragma unroll
                for (int nt = 0; nt < 4; ++nt) {
                    mma_bf16(acc[mt][nt], ah, &bh[nt * 2]);
                    mma_bf16(acc[mt][nt], ah, &bl[nt * 2]);
                    mma_bf16(acc[mt][nt], al, &bh[nt * 2]);
                }
            }
        }
        __syncthreads();
    }

    // epilogue: trunc-split, store interleaved [128 hi][128 lo] per node row
#pragma unroll
    for (int mt = 0; mt < 4; ++mt) {
        int ra = row0 + m0 + mt * 16 + (lane >> 2);
#pragma unroll
        for (int nt = 0; nt < 4; ++nt) {
            int cb = n0 + nt * 8 + 2 * (lane & 3);
            uint32_t hp, lp;
            split2(acc[mt][nt][0], acc[mt][nt][1], hp, lp);
            *(uint32_t*)&g_xs[(size_t)ra * 256 + cb]       = hp;
            *(uint32_t*)&g_xs[(size_t)ra * 256 + 128 + cb] = lp;
            split2(acc[mt][nt][2], acc[mt][nt][3], hp, lp);
            *(uint32_t*)&g_xs[(size_t)(ra + 8) * 256 + cb]       = hp;
            *(uint32_t*)&g_xs[(size_t)(ra + 8) * 256 + 128 + cb] = lp;
        }
    }
}

// ---------------------------------------------------------------------------
// Kernel B: topk (register rank), cp.async gather, symmetric 3-tile Gram,
//           in-fragment dist, fast softmax, X^T-oriented mma agg.
//           1 CTA/node, 128 threads.
// ---------------------------------------------------------------------------
#define BPITCH 136

__global__ __launch_bounds__(128) void node_kernel(const float* __restrict__ ew,
                                                   const int*   __restrict__ nbr,
                                                   const float* __restrict__ bias,
                                                   float*       __restrict__ out,
                                                   int n)
{
    __shared__ __align__(16) __nv_bfloat16 xhi[32 * BPITCH];
    __shared__ __align__(16) __nv_bfloat16 xlo[32 * BPITCH];
    __shared__ float selw[32];
    __shared__ int   selid[32];
    __shared__ float ssq[32];
    __shared__ float sdA[32];
    __shared__ float sdB[32];
    __shared__ __align__(4) unsigned short srelh[32];
    __shared__ __align__(4) unsigned short srell[32];

    const int node = blockIdx.x;
    const int tid  = threadIdx.x;
    const int lane = tid & 31;
    const int wrp  = tid >> 5;

    // --- top-32 of 49: rank via uniform vector loads, no smem staging ---
    if (tid < DEG + 1) {
        float v; int myid;
        if (tid < DEG) {
            v    = ew[(size_t)node * DEG + tid];
            myid = nbr[(size_t)node * DEG + tid];
        } else {
            v = 1.0f; myid = node;
        }
        int rank = (1.0f > v) ? 1 : 0;   // self-loop j=48: j<tid never for tid<=48
        const float4* row = (const float4*)(ew + (size_t)node * DEG);
#pragma unroll
        for (int c = 0; c < 12; ++c) {
            float4 w4 = row[c];
            int j0 = c * 4;
            rank += (w4.x > v) || (w4.x == v && (j0 + 0) < tid);
            rank += (w4.y > v) || (w4.y == v && (j0 + 1) < tid);
            rank += (w4.z > v) || (w4.z == v && (j0 + 2) < tid);
            rank += (w4.w > v) || (w4.w == v && (j0 + 3) < tid);
        }
        if (rank < KSEL) { selw[rank] = v; selid[rank] = myid; }
    }
    __syncthreads();

    // --- gather via cp.async: 1 row = 512B = 32 lanes x 16B ---
    {
        const int r0 = wrp * 8;
        const uint32_t hbase0 = smem_u32(xhi);
        const uint32_t lbase0 = smem_u32(xlo);
        const uint32_t dbase  = (lane < 16 ? hbase0 : lbase0) + (lane & 15) * 16;
#pragma unroll
        for (int r = 0; r < 8; ++r) {
            const int row = r0 + r;
            const char* src = (const char*)g_xs + (size_t)selid[row] * 512 + lane * 16;
            uint32_t dst = dbase + (uint32_t)(row * (BPITCH * 2));
            asm volatile("cp.async.ca.shared.global [%0], [%1], 16;"
                         :: "r"(dst), "l"(src));
        }
        asm volatile("cp.async.commit_group;");
        asm volatile("cp.async.wait_group 0;");
    }
    __syncthreads();

    // --- Gram, 3 tiles: w0 diag(0,0) A=B aliased, w1 diag(16,16), w2 offdiag ---
    const uint32_t hbase = smem_u32(xhi);
    const uint32_t lbase = smem_u32(xlo);
    const int p = lane >> 2;
    const int q = lane & 3;
    float c0f[4] = {0.f, 0.f, 0.f, 0.f};
    float c1f[4] = {0.f, 0.f, 0.f, 0.f};

    if (wrp < 2) {
        const int m0 = wrp * 16;
        const int rsel = lane >> 3, rin = lane & 7;
        const uint32_t a_off = (uint32_t)((m0 + (rsel & 1) * 8 + rin) * BPITCH
                                          + (rsel >> 1) * 8) * 2;
#pragma unroll
        for (int kc = 0; kc < 8; ++kc) {
            uint32_t ah[4], al[4];
            ldmatrix_x4(ah, hbase + a_off + kc * 32);
            ldmatrix_x4(al, lbase + a_off + kc * 32);
            uint32_t bh0[2] = {ah[0], ah[2]}, bh1[2] = {ah[1], ah[3]};
            uint32_t bl0[2] = {al[0], al[2]}, bl1[2] = {al[1], al[3]};
            mma_bf16(c0f, ah, bh0); mma_bf16(c0f, ah, bl0); mma_bf16(c0f, al, bh0);
            mma_bf16(c1f, ah, bh1); mma_bf16(c1f, ah, bl1); mma_bf16(c1f, al, bh1);
        }
        if (p == 2 * q)     { ssq[m0 + p] = c0f[0]; ssq[m0 + p + 8] = c1f[2]; }
        if (p == 2 * q + 1) { ssq[m0 + p] = c0f[1]; ssq[m0 + p + 8] = c1f[3]; }
    } else if (wrp == 2) {
        const int rsel = lane >> 3, rin = lane & 7;
        const uint32_t a_off = (uint32_t)(((rsel & 1) * 8 + rin) * BPITCH
                                          + (rsel >> 1) * 8) * 2;
        const uint32_t b_off = (uint32_t)((16 + (rsel >> 1) * 8 + rin) * BPITCH
                                          + (rsel & 1) * 8) * 2;
#pragma unroll
        for (int kc = 0; kc < 8; ++kc) {
            uint32_t ah[4], al[4], bh[4], bl[4];
            ldmatrix_x4(ah, hbase + a_off + kc * 32);
            ldmatrix_x4(al, lbase + a_off + kc * 32);
            ldmatrix_x4(bh, hbase + b_off + kc * 32);
            ldmatrix_x4(bl, lbase + b_off + kc * 32);
            mma_bf16(c0f, ah, &bh[0]); mma_bf16(c0f, ah, &bl[0]); mma_bf16(c0f, al, &bh[0]);
            mma_bf16(c1f, ah, &bh[2]); mma_bf16(c1f, ah, &bl[2]); mma_bf16(c1f, al, &bh[2]);
        }
    }
    __syncthreads();   // ssq visible to all

    // --- dist partials ---
    if (wrp < 2) {
        const int m0 = wrp * 16;
        const int b0 = m0 + 2 * q, b1 = b0 + 1, b2 = b0 + 8, b3 = b2 + 1;
        const float w0 = selw[b0], w1 = selw[b1], w2 = selw[b2], w3 = selw[b3];
        const float s0 = ssq[b0], s1 = ssq[b1], s2 = ssq[b2], s3 = ssq[b3];
        const float sqa  = ssq[m0 + p];
        const float sqa8 = ssq[m0 + p + 8];

        float d, part = 0.f, part8 = 0.f;
        d = sqa  + s0 - 2.f * c0f[0]; part  = fmaf(w0, (d > 0.f) ? sqrt_approx(d) : 0.f, part);
        d = sqa  + s1 - 2.f * c0f[1]; part  = fmaf(w1, (d > 0.f) ? sqrt_approx(d) : 0.f, part);
        d = sqa  + s2 - 2.f * c1f[0]; part  = fmaf(w2, (d > 0.f) ? sqrt_approx(d) : 0.f, part);
        d = sqa  + s3 - 2.f * c1f[1]; part  = fmaf(w3, (d > 0.f) ? sqrt_approx(d) : 0.f, part);
        d = sqa8 + s0 - 2.f * c0f[2]; part8 = fmaf(w0, (d > 0.f) ? sqrt_approx(d) : 0.f, part8);
        d = sqa8 + s1 - 2.f * c0f[3]; part8 = fmaf(w1, (d > 0.f) ? sqrt_approx(d) : 0.f, part8);
        d = sqa8 + s2 - 2.f * c1f[2]; part8 = fmaf(w2, (d > 0.f) ? sqrt_approx(d) : 0.f, part8);
        d = sqa8 + s3 - 2.f * c1f[3]; part8 = fmaf(w3, (d > 0.f) ? sqrt_approx(d) : 0.f, part8);

        part  += __shfl_down_sync(0xffffffffu, part, 2);
        part  += __shfl_down_sync(0xffffffffu, part, 1);
        part8 += __shfl_down_sync(0xffffffffu, part8, 2);
        part8 += __shfl_down_sync(0xffffffffu, part8, 1);
        if (q == 0) { sdA[m0 + p] = part; sdA[m0 + p + 8] = part8; }
    } else if (wrp == 2) {
        const int cA = 16 + 2 * q, cB = cA + 1, cC = cA + 8, cD = cC + 1;
        const float wA = selw[cA], wB = selw[cB], wC = selw[cC], wD = selw[cD];
        const float sA = ssq[cA], sB = ssq[cB], sC = ssq[cC], sD = ssq[cD];
        const float sqa  = ssq[p];
        const float sqa8 = ssq[p + 8];
        const float wp   = selw[p];
        const float wp8  = selw[p + 8];

        float d;
        d = sqa  + sA - 2.f * c0f[0]; float dpA = (d > 0.f) ? sqrt_approx(d) : 0.f;
        d = sqa  + sB - 2.f * c0f[1]; float dpB = (d > 0.f) ? sqrt_approx(d) : 0.f;
        d = sqa  + sC - 2.f * c1f[0]; float dpC = (d > 0.f) ? sqrt_approx(d) : 0.f;
        d = sqa  + sD - 2.f * c1f[1]; float dpD = (d > 0.f) ? sqrt_approx(d) : 0.f;
        d = sqa8 + sA - 2.f * c0f[2]; float d8A = (d > 0.f) ? sqrt_approx(d) : 0.f;
        d = sqa8 + sB - 2.f * c0f[3]; float d8B = (d > 0.f) ? sqrt_approx(d) : 0.f;
        d = sqa8 + sC - 2.f * c1f[2]; float d8C = (d > 0.f) ? sqrt_approx(d) : 0.f;
        d = sqa8 + sD - 2.f * c1f[3]; float d8D = (d > 0.f) ? sqrt_approx(d) : 0.f;

        float part  = wA * dpA + wB * dpB + wC * dpC + wD * dpD;
        float part8 = wA * d8A + wB * d8B + wC * d8C + wD * d8D;
        part  += __shfl_down_sync(0xffffffffu, part, 2);
        part  += __shfl_down_sync(0xffffffffu, part, 1);
        part8 += __shfl_down_sync(0xffffffffu, part8, 2);
        part8 += __shfl_down_sync(0xffffffffu, part8, 1);
        if (q == 0) { sdB[p] = part; sdB[p + 8] = part8; }

        float colA = wp * dpA + wp8 * d8A;
        float colB = wp * dpB + wp8 * d8B;
        float colC = wp * dpC + wp8 * d8C;
        float colD = wp * dpD + wp8 * d8D;
#pragma unroll
        for (int off = 4; off <= 16; off <<= 1) {
            colA += __shfl_xor_sync(0xffffffffu, colA, off);
            colB += __shfl_xor_sync(0xffffffffu, colB, off);
            colC += __shfl_xor_sync(0xffffffffu, colC, off);
            colD += __shfl_xor_sync(0xffffffffu, colD, off);
        }
        if (lane < 4) {
            *(float2*)&sdB[16 + 2 * lane] = make_float2(colA, colB);
            *(float2*)&sdB[24 + 2 * lane] = make_float2(colC, colD);
        }
    }
    __syncthreads();

    // --- softmax(-dist) * tw, renormalized; emit rel hi/lo (warp 0) ---
    if (tid < 32) {
        float v = sdA[tid] + sdB[tid];
        float m = v;
#pragma unroll
        for (int off = 16; off; off >>= 1)
            m = fminf(m, __shfl_xor_sync(0xffffffffu, m, off));
        float r = __expf(m - v) * selw[tid];
        float s = r;
#pragma unroll
        for (int off = 16; off; off >>= 1)
            s += __shfl_xor_sync(0xffffffffu, s, off);
        float rr = __fdividef(r, s);
        uint32_t bits = __float_as_uint(rr);
        srelh[tid] = (unsigned short)(bits >> 16);
        float rl = rr - __uint_as_float(bits & 0xffff0000u);
        srell[tid] = __bfloat16_as_ushort(__float2bfloat16_rn(rl));
    }
    __syncthreads();

    // --- aggregation: out^T = X^T @ rel via mma; warp w -> dout [32w, 32w+32) ---
    {
        const uint32_t* relh32 = (const uint32_t*)srelh;
        const uint32_t* rell32 = (const uint32_t*)srell;
        const int d0 = wrp * 32;
        const int g = lane >> 3, rin = lane & 7;

        float cacc[2][4];
#pragma unroll
        for (int i = 0; i < 2; ++i)
#pragma unroll
            for (int j = 0; j < 4; ++j) cacc[i][j] = 0.f;

#pragma unroll
        for (int kc = 0; kc < 2; ++kc) {
            // B-frag: col 0 = rel[k]; only lanes 0-3 (n=0) feed D col 0
            uint32_t bh[2], bl[2];
            bh[0] = relh32[kc * 8 + q];
            bh[1] = relh32[kc * 8 + 4 + q];
            bl[0] = rell32[kc * 8 + q];
            bl[1] = rell32[kc * 8 + 4 + q];

#pragma unroll
            for (int mt = 0; mt < 2; ++mt) {
                // A = X^T tile via trans ldmatrix:
                // frag blocks (m0-7,k0-7),(m8-15,k0-7),(m0-7,k8-15),(m8-15,k8-15)
                uint32_t aoff = (uint32_t)(((kc * 16 + (g >> 1) * 8 + rin) * BPITCH
                                            + d0 + mt * 16 + (g & 1) * 8) * 2);
                uint32_t ah[4], al[4];
                ldmatrix_x4_trans(ah, hbase + aoff);
                ldmatrix_x4_trans(al, lbase + aoff);

                mma_bf16(cacc[mt], ah, bh);
                mma_bf16(cacc[mt], ah, bl);
                mma_bf16(cacc[mt], al, bh);
            }
        }

        // D col 0: lanes with (lane&3)==0 hold rows p (c0) and p+8 (c2)
        if (q == 0) {
#pragma unroll
            for (int mt = 0; mt < 2; ++mt) {
                int dd = d0 + mt * 16 + p;
                out[(size_t)node * DOUT + dd]     = cacc[mt][0] + bias[dd];
                out[(size_t)node * DOUT + dd + 8] = cacc[mt][2] + bias[dd + 8];
            }
        }
    }
}

// ---------------------------------------------------------------------------
// Launch
// ---------------------------------------------------------------------------
extern "C" void kernel_launch(void* const* d_in, const int* in_sizes, int n_in,
                              void* d_out, int out_size)
{
    const float* feat   = (const float*)d_in[0];
    const float* ew     = (const float*)d_in[1];
    const float* weight = (const float*)d_in[2];
    const float* bias   = (const float*)d_in[3];
    const int*   nbr    = (const int*)  d_in[4];
    float*       out    = (float*)d_out;

    int n = in_sizes[0] / DIN;

    wsplit_kernel<<<64, 256>>>(weight);
    gemm_kernel<<<(n + 127) / 128, 256>>>(feat, n);
    node_kernel<<<n, 128>>>(ew, nbr, bias, out, n);
}